// round 12
// baseline (speedup 1.0000x reference)
#include <cuda_runtime.h>
#include <cuda_bf16.h>
#include <cuda_fp16.h>
#include <stdint.h>

#define NN 100000
#define NN_PAD 100096
#define NE 1600000
#define IN_DIM 128
#define HID_DIM 256
#define OUT_DIM 64

// ---------------- device scratch ----------------
__device__ __align__(16) int   g_deg_src[NN];
__device__ __align__(16) int   g_deg_dst[NN];
__device__ __align__(16) int   g_rowptr[NN + 1];   // CSR by dst
__device__ __align__(16) int   g_cursor[NN];
__device__ __align__(16) int   g_esrc[NE];         // src ids bucketed by dst
__device__ __align__(16) float g_norm_src[NN];
__device__ __align__(16) float g_norm_dst[NN];
__device__ __align__(16) __half g_h16[(size_t)NN * IN_DIM];          // fp16(h * norm_src[row])
__device__ __align__(16) __nv_bfloat16 g_xa_hi[(size_t)NN_PAD * IN_DIM];
__device__ __align__(16) __nv_bfloat16 g_xa_lo[(size_t)NN_PAD * IN_DIM];
__device__ __align__(16) __nv_bfloat16 g_w1t_hi[HID_DIM * IN_DIM];   // [n][k]
__device__ __align__(16) __nv_bfloat16 g_w1t_lo[HID_DIM * IN_DIM];
__device__ __align__(16) __nv_bfloat16 g_w2t_hi[OUT_DIM * HID_DIM];  // [n][k]
__device__ __align__(16) __nv_bfloat16 g_w2t_lo[OUT_DIM * HID_DIM];
__device__ __align__(16) __nv_bfloat16 g_hid_hi[(size_t)NN_PAD * HID_DIM];
__device__ __align__(16) __nv_bfloat16 g_hid_lo[(size_t)NN_PAD * HID_DIM];
__device__ __align__(16) __half g_ypre16[(size_t)NN * OUT_DIM];      // fp16((hidden@W2)*norm_src)

__device__ __forceinline__ void split_bf16(float v, __nv_bfloat16& hi, __nv_bfloat16& lo) {
    hi = __float2bfloat16(v);
    lo = __float2bfloat16(v - __bfloat162float(hi));
}

#define MMA_BF16(d, a, b0, b1)                                                  \
    asm volatile("mma.sync.aligned.m16n8k16.row.col.f32.bf16.bf16.f32 "         \
                 "{%0,%1,%2,%3}, {%4,%5,%6,%7}, {%8,%9}, {%0,%1,%2,%3};"        \
                 : "+f"(d[0]), "+f"(d[1]), "+f"(d[2]), "+f"(d[3])               \
                 : "r"(a[0]), "r"(a[1]), "r"(a[2]), "r"(a[3]), "r"(b0), "r"(b1))

__device__ __forceinline__ void cp16(void* smem_dst, const void* gmem_src) {
    uint32_t s = (uint32_t)__cvta_generic_to_shared(smem_dst);
    asm volatile("cp.async.cg.shared.global [%0], [%1], 16;" :: "r"(s), "l"(gmem_src) : "memory");
}
#define CP_COMMIT() asm volatile("cp.async.commit_group;" ::: "memory")
#define CP_WAIT(n)  asm volatile("cp.async.wait_group %0;" :: "n"(n) : "memory")

// ---------------- zero init: degree counters + pad rows ----------------
__global__ void k_zero() {
    int i = blockIdx.x * blockDim.x + threadIdx.x;
    int stride = gridDim.x * blockDim.x;
    for (int j = i; j < NN; j += stride) { g_deg_src[j] = 0; g_deg_dst[j] = 0; }
    // xa pad rows (read by gemm1 A tiles) must be zero: uint4 = 8 bf16
    const int xa_pad = (NN_PAD - NN) * (IN_DIM / 8);   // 1536
    uint4* xh = reinterpret_cast<uint4*>(g_xa_hi + (size_t)NN * IN_DIM);
    uint4* xl = reinterpret_cast<uint4*>(g_xa_lo + (size_t)NN * IN_DIM);
    const uint4 z4 = make_uint4(0u, 0u, 0u, 0u);
    for (int j = i; j < xa_pad; j += stride) { xh[j] = z4; xl[j] = z4; }
    // hid pad rows (read by gemm2 A tiles) must be zero
    const int hid_pad = (NN_PAD - NN) * (HID_DIM / 8);
    uint4* hh = reinterpret_cast<uint4*>(g_hid_hi + (size_t)NN * HID_DIM);
    uint4* hl = reinterpret_cast<uint4*>(g_hid_lo + (size_t)NN * HID_DIM);
    for (int j = i; j < hid_pad; j += stride) { hh[j] = z4; hl[j] = z4; }
}

// ---------------- degrees ----------------
__global__ void k_degree(const int* __restrict__ src, const int* __restrict__ dst, int n_edges) {
    int i = blockIdx.x * blockDim.x + threadIdx.x;
    int stride = gridDim.x * blockDim.x;
    for (int e = i; e < n_edges; e += stride) {
        atomicAdd(&g_deg_src[src[e]], 1);
        atomicAdd(&g_deg_dst[dst[e]], 1);
    }
}

// ---------------- norms ----------------
__global__ void k_norm(int n_nodes) {
    int i = blockIdx.x * blockDim.x + threadIdx.x;
    if (i < n_nodes) {
        g_norm_src[i] = rsqrtf((float)max(g_deg_src[i], 1));
        g_norm_dst[i] = rsqrtf((float)max(g_deg_dst[i], 1));
    }
}

// ---------------- single-block scan of DST degrees -> rowptr, cursor ----------------
__global__ __launch_bounds__(1024) void k_scan() {
    __shared__ int sh[1024];
    const int tid = threadIdx.x;
    const int per = (NN + 1023) / 1024;   // 98
    const int base = tid * per;
    int sum = 0;
    for (int i = 0; i < per; i++) {
        int idx = base + i;
        if (idx < NN) sum += g_deg_dst[idx];
    }
    sh[tid] = sum;
    __syncthreads();
    for (int off = 1; off < 1024; off <<= 1) {
        int t = (tid >= off) ? sh[tid - off] : 0;
        __syncthreads();
        sh[tid] += t;
        __syncthreads();
    }
    int run = sh[tid] - sum;
    for (int i = 0; i < per; i++) {
        int idx = base + i;
        if (idx < NN) {
            g_rowptr[idx] = run;
            g_cursor[idx] = run;
            run += g_deg_dst[idx];
        }
    }
    if (tid == 1023) g_rowptr[NN] = run;
}

// ---------------- scatter edge srcs into dst buckets ----------------
__global__ void k_scatter(const int* __restrict__ src, const int* __restrict__ dst, int n_edges) {
    int i = blockIdx.x * blockDim.x + threadIdx.x;
    int stride = gridDim.x * blockDim.x;
    for (int e = i; e < n_edges; e += stride) {
        int d = dst[e];
        int pos = atomicAdd(&g_cursor[d], 1);
        g_esrc[pos] = src[e];
    }
}

// ---------------- prep: h16 = fp16(h * norm_src[row]); split weights ----------------
__global__ void k_prep(const float* __restrict__ h,
                       const float* __restrict__ W1, const float* __restrict__ W2) {
    int i = blockIdx.x * blockDim.x + threadIdx.x;
    int stride = gridDim.x * blockDim.x;
    // weights
    const int n1 = HID_DIM * IN_DIM;     // 32768
    const int n2 = OUT_DIM * HID_DIM;    // 16384
    for (int j = i; j < n1 + n2; j += stride) {
        if (j < n1) {
            int n = j / IN_DIM, k = j % IN_DIM;
            float v = W1[(size_t)k * HID_DIM + n];
            __nv_bfloat16 hi, lo;
            split_bf16(v, hi, lo);
            g_w1t_hi[j] = hi; g_w1t_lo[j] = lo;
        } else {
            int jj = j - n1;
            int n = jj / HID_DIM, k = jj % HID_DIM;
            float v = W2[(size_t)k * OUT_DIM + n];
            __nv_bfloat16 hi, lo;
            split_bf16(v, hi, lo);
            g_w2t_hi[jj] = hi; g_w2t_lo[jj] = lo;
        }
    }
    // h conversion with norm_src folded in
    const int nh4 = NN * (IN_DIM / 4);
    for (int j = i; j < nh4; j += stride) {
        int row = j >> 5;   // 32 float4 per row
        float ns = g_norm_src[row];
        float4 v = reinterpret_cast<const float4*>(h)[j];
        __half2 a = __floats2half2_rn(v.x * ns, v.y * ns);
        __half2 b = __floats2half2_rn(v.z * ns, v.w * ns);
        uint2 pk;
        pk.x = *reinterpret_cast<uint32_t*>(&a);
        pk.y = *reinterpret_cast<uint32_t*>(&b);
        reinterpret_cast<uint2*>(g_h16)[j] = pk;
    }
}

// ---------------- SpMM1 (CSR by dst, no atomics): xa = split(norm_dst * sum h16[src]) ----------------
// warp per dst node; lane covers 4 halves (8B); 8 gathers in flight
__global__ void k_spmm1(int n_nodes) {
    int node = (blockIdx.x * blockDim.x + threadIdx.x) >> 5;
    if (node >= n_nodes) return;
    int lane = threadIdx.x & 31;
    int e = g_rowptr[node];
    const int end = g_rowptr[node + 1];
    const uint2* h2 = reinterpret_cast<const uint2*>(g_h16);
    float4 acc = make_float4(0.f, 0.f, 0.f, 0.f);
    for (; e + 8 <= end; e += 8) {
        int s[8];
        #pragma unroll
        for (int i = 0; i < 8; i++) s[i] = __ldg(&g_esrc[e + i]);
        uint2 v[8];
        #pragma unroll
        for (int i = 0; i < 8; i++) v[i] = h2[(size_t)s[i] * 32 + lane];
        #pragma unroll
        for (int i = 0; i < 8; i++) {
            __half2 a = *reinterpret_cast<__half2*>(&v[i].x);
            __half2 b = *reinterpret_cast<__half2*>(&v[i].y);
            float2 fa = __half22float2(a);
            float2 fb = __half22float2(b);
            acc.x += fa.x; acc.y += fa.y; acc.z += fb.x; acc.w += fb.y;
        }
    }
    for (; e < end; e++) {
        int s = __ldg(&g_esrc[e]);
        uint2 v = h2[(size_t)s * 32 + lane];
        __half2 a = *reinterpret_cast<__half2*>(&v.x);
        __half2 b = *reinterpret_cast<__half2*>(&v.y);
        float2 fa = __half22float2(a);
        float2 fb = __half22float2(b);
        acc.x += fa.x; acc.y += fa.y; acc.z += fb.x; acc.w += fb.y;
    }
    float nd = g_norm_dst[node];
    acc.x *= nd; acc.y *= nd; acc.z *= nd; acc.w *= nd;
    __nv_bfloat16 h0, l0, h1, l1, h2b, l2, h3, l3;
    split_bf16(acc.x, h0, l0); split_bf16(acc.y, h1, l1);
    split_bf16(acc.z, h2b, l2); split_bf16(acc.w, h3, l3);
    uint2 ph, pl;
    __nv_bfloat162 t0(h0, h1), t1(h2b, h3);
    ph.x = *reinterpret_cast<uint32_t*>(&t0);
    ph.y = *reinterpret_cast<uint32_t*>(&t1);
    __nv_bfloat162 u0(l0, l1), u1(l2, l3);
    pl.x = *reinterpret_cast<uint32_t*>(&u0);
    pl.y = *reinterpret_cast<uint32_t*>(&u1);
    size_t off = (size_t)node * 32 + lane;
    reinterpret_cast<uint2*>(g_xa_hi)[off] = ph;
    reinterpret_cast<uint2*>(g_xa_lo)[off] = pl;
}

// ---------------- GEMM tiles ----------------
#define BM 128
#define BN 64
#define BK 32
#define KPAD 40
#define STAGE_ELEMS 15360
#define SMEM_BYTES (2 * STAGE_ELEMS * 2)

// GEMM1: hidden = relu(xa @ W1 + b1) * clip(p,0,1); cp.async double-buffered
__global__ __launch_bounds__(256) void k_gemm1(const float* __restrict__ b1,
                                               const float* __restrict__ p,
                                               int n_nodes) {
    extern __shared__ __nv_bfloat16 smem[];
    const int m0 = blockIdx.x * BM;
    const int n0 = blockIdx.y * BN;
    const int tid = threadIdx.x;
    const int lane = tid & 31;
    const int wid = tid >> 5;
    const int warp_m = wid >> 2;
    const int warp_n = wid & 3;
    const int bn = tid >> 2;
    const int bq = tid & 3;

    auto load_stage = [&](int s, int k0) {
        __nv_bfloat16* As_hi = smem + s * STAGE_ELEMS;
        __nv_bfloat16* As_lo = As_hi + 5120;
        __nv_bfloat16* Bs_hi = As_hi + 10240;
        __nv_bfloat16* Bs_lo = As_hi + 12800;
        #pragma unroll
        for (int i = 0; i < 2; i++) {
            int idx = tid + 256 * i;
            int row = idx >> 2;
            int q = idx & 3;
            cp16(&As_hi[row * KPAD + 8 * q], &g_xa_hi[(size_t)(m0 + row) * IN_DIM + k0 + 8 * q]);
            cp16(&As_lo[row * KPAD + 8 * q], &g_xa_lo[(size_t)(m0 + row) * IN_DIM + k0 + 8 * q]);
        }
        cp16(&Bs_hi[bn * KPAD + 8 * bq], &g_w1t_hi[(size_t)(n0 + bn) * IN_DIM + k0 + 8 * bq]);
        cp16(&Bs_lo[bn * KPAD + 8 * bq], &g_w1t_lo[(size_t)(n0 + bn) * IN_DIM + k0 + 8 * bq]);
        CP_COMMIT();
    };

    float acc[4][2][4];
    #pragma unroll
    for (int i = 0; i < 4; i++)
        #pragma unroll
        for (int j = 0; j < 2; j++)
            #pragma unroll
            for (int q = 0; q < 4; q++) acc[i][j][q] = 0.f;

    const int K_ITERS = IN_DIM / BK;
    load_stage(0, 0);
    for (int it = 0; it < K_ITERS; it++) {
        if (it + 1 < K_ITERS) {
            load_stage((it + 1) & 1, (it + 1) * BK);
            CP_WAIT(1);
        } else {
            CP_WAIT(0);
        }
        __syncthreads();

        __nv_bfloat16* As_hi = smem + (it & 1) * STAGE_ELEMS;
        __nv_bfloat16* As_lo = As_hi + 5120;
        __nv_bfloat16* Bs_hi = As_hi + 10240;
        __nv_bfloat16* Bs_lo = As_hi + 12800;

        #pragma unroll
        for (int ks = 0; ks < 2; ks++) {
            const int kc = ks * 16 + 2 * (lane & 3);
            uint32_t ah[4][4], al[4][4];
            #pragma unroll
            for (int i = 0; i < 4; i++) {
                int r = warp_m * 64 + i * 16 + (lane >> 2);
                ah[i][0] = *reinterpret_cast<uint32_t*>(&As_hi[r * KPAD + kc]);
                ah[i][1] = *reinterpret_cast<uint32_t*>(&As_hi[(r + 8) * KPAD + kc]);
                ah[i][2] = *reinterpret_cast<uint32_t*>(&As_hi[r * KPAD + kc + 8]);
                ah[i][3] = *reinterpret_cast<uint32_t*>(&As_hi[(r + 8) * KPAD + kc + 8]);
                al[i][0] = *reinterpret_cast<uint32_t*>(&As_lo[r * KPAD + kc]);
                al[i][1] = *reinterpret_cast<uint32_t*>(&As_lo[(r + 8) * KPAD + kc]);
                al[i][2] = *reinterpret_cast<uint32_t*>(&As_lo[r * KPAD + kc + 8]);
                al[i][3] = *reinterpret_cast<uint32_t*>(&As_lo[(r + 8) * KPAD + kc + 8]);
            }
            #pragma unroll
            for (int j = 0; j < 2; j++) {
                int c = warp_n * 16 + j * 8 + (lane >> 2);
                uint32_t bh0 = *reinterpret_cast<uint32_t*>(&Bs_hi[c * KPAD + kc]);
                uint32_t bh1 = *reinterpret_cast<uint32_t*>(&Bs_hi[c * KPAD + kc + 8]);
                uint32_t bl0 = *reinterpret_cast<uint32_t*>(&Bs_lo[c * KPAD + kc]);
                uint32_t bl1 = *reinterpret_cast<uint32_t*>(&Bs_lo[c * KPAD + kc + 8]);
                #pragma unroll
                for (int i = 0; i < 4; i++) {
                    MMA_BF16(acc[i][j], ah[i], bh0, bh1);
                    MMA_BF16(acc[i][j], ah[i], bl0, bl1);
                    MMA_BF16(acc[i][j], al[i], bh0, bh1);
                }
            }
        }
        __syncthreads();
    }

    #pragma unroll
    for (int i = 0; i < 4; i++) {
        int r = warp_m * 64 + i * 16 + (lane >> 2);
        #pragma unroll
        for (int j = 0; j < 2; j++) {
            int c0 = n0 + warp_n * 16 + j * 8 + 2 * (lane & 3);
            float bb0 = b1[c0], bb1 = b1[c0 + 1];
            float p0 = fminf(fmaxf(p[c0], 0.f), 1.f);
            float p1 = fminf(fmaxf(p[c0 + 1], 0.f), 1.f);
            #pragma unroll
            for (int hrow = 0; hrow < 2; hrow++) {
                int grow = m0 + r + 8 * hrow;
                if (grow >= n_nodes) continue;
                float v0 = fmaxf(acc[i][j][2 * hrow + 0] + bb0, 0.f) * p0;
                float v1 = fmaxf(acc[i][j][2 * hrow + 1] + bb1, 0.f) * p1;
                __nv_bfloat16 h0, l0, h1, l1;
                split_bf16(v0, h0, l0);
                split_bf16(v1, h1, l1);
                *reinterpret_cast<__nv_bfloat162*>(&g_hid_hi[(size_t)grow * HID_DIM + c0]) = __nv_bfloat162(h0, h1);
                *reinterpret_cast<__nv_bfloat162*>(&g_hid_lo[(size_t)grow * HID_DIM + c0]) = __nv_bfloat162(l0, l1);
            }
        }
    }
}

// GEMM2: ypre16 = fp16((hidden @ W2) * norm_src[row]); cp.async double-buffered
__global__ __launch_bounds__(256) void k_gemm2(int n_nodes) {
    extern __shared__ __nv_bfloat16 smem[];
    const int m0 = blockIdx.x * BM;
    const int tid = threadIdx.x;
    const int lane = tid & 31;
    const int wid = tid >> 5;
    const int warp_m = wid >> 2;
    const int warp_n = wid & 3;
    const int bn = tid >> 2;
    const int bq = tid & 3;

    auto load_stage = [&](int s, int k0) {
        __nv_bfloat16* As_hi = smem + s * STAGE_ELEMS;
        __nv_bfloat16* As_lo = As_hi + 5120;
        __nv_bfloat16* Bs_hi = As_hi + 10240;
        __nv_bfloat16* Bs_lo = As_hi + 12800;
        #pragma unroll
        for (int i = 0; i < 2; i++) {
            int idx = tid + 256 * i;
            int row = idx >> 2;
            int q = idx & 3;
            cp16(&As_hi[row * KPAD + 8 * q], &g_hid_hi[(size_t)(m0 + row) * HID_DIM + k0 + 8 * q]);
            cp16(&As_lo[row * KPAD + 8 * q], &g_hid_lo[(size_t)(m0 + row) * HID_DIM + k0 + 8 * q]);
        }
        cp16(&Bs_hi[bn * KPAD + 8 * bq], &g_w2t_hi[(size_t)bn * HID_DIM + k0 + 8 * bq]);
        cp16(&Bs_lo[bn * KPAD + 8 * bq], &g_w2t_lo[(size_t)bn * HID_DIM + k0 + 8 * bq]);
        CP_COMMIT();
    };

    float acc[4][2][4];
    #pragma unroll
    for (int i = 0; i < 4; i++)
        #pragma unroll
        for (int j = 0; j < 2; j++)
            #pragma unroll
            for (int q = 0; q < 4; q++) acc[i][j][q] = 0.f;

    const int K_ITERS = HID_DIM / BK;
    load_stage(0, 0);
    for (int it = 0; it < K_ITERS; it++) {
        if (it + 1 < K_ITERS) {
            load_stage((it + 1) & 1, (it + 1) * BK);
            CP_WAIT(1);
        } else {
            CP_WAIT(0);
        }
        __syncthreads();

        __nv_bfloat16* As_hi = smem + (it & 1) * STAGE_ELEMS;
        __nv_bfloat16* As_lo = As_hi + 5120;
        __nv_bfloat16* Bs_hi = As_hi + 10240;
        __nv_bfloat16* Bs_lo = As_hi + 12800;

        #pragma unroll
        for (int ks = 0; ks < 2; ks++) {
            const int kc = ks * 16 + 2 * (lane & 3);
            uint32_t ah[4][4], al[4][4];
            #pragma unroll
            for (int i = 0; i < 4; i++) {
                int r = warp_m * 64 + i * 16 + (lane >> 2);
                ah[i][0] = *reinterpret_cast<uint32_t*>(&As_hi[r * KPAD + kc]);
                ah[i][1] = *reinterpret_cast<uint32_t*>(&As_hi[(r + 8) * KPAD + kc]);
                ah[i][2] = *reinterpret_cast<uint32_t*>(&As_hi[r * KPAD + kc + 8]);
                ah[i][3] = *reinterpret_cast<uint32_t*>(&As_hi[(r + 8) * KPAD + kc + 8]);
                al[i][0] = *reinterpret_cast<uint32_t*>(&As_lo[r * KPAD + kc]);
                al[i][1] = *reinterpret_cast<uint32_t*>(&As_lo[(r + 8) * KPAD + kc]);
                al[i][2] = *reinterpret_cast<uint32_t*>(&As_lo[r * KPAD + kc + 8]);
                al[i][3] = *reinterpret_cast<uint32_t*>(&As_lo[(r + 8) * KPAD + kc + 8]);
            }
            #pragma unroll
            for (int j = 0; j < 2; j++) {
                int c = warp_n * 16 + j * 8 + (lane >> 2);
                uint32_t bh0 = *reinterpret_cast<uint32_t*>(&Bs_hi[c * KPAD + kc]);
                uint32_t bh1 = *reinterpret_cast<uint32_t*>(&Bs_hi[c * KPAD + kc + 8]);
                uint32_t bl0 = *reinterpret_cast<uint32_t*>(&Bs_lo[c * KPAD + kc]);
                uint32_t bl1 = *reinterpret_cast<uint32_t*>(&Bs_lo[c * KPAD + kc + 8]);
                #pragma unroll
                for (int i = 0; i < 4; i++) {
                    MMA_BF16(acc[i][j], ah[i], bh0, bh1);
                    MMA_BF16(acc[i][j], ah[i], bl0, bl1);
                    MMA_BF16(acc[i][j], al[i], bh0, bh1);
                }
            }
        }
        __syncthreads();
    }

    #pragma unroll
    for (int i = 0; i < 4; i++) {
        int r = warp_m * 64 + i * 16 + (lane >> 2);
        #pragma unroll
        for (int j = 0; j < 2; j++) {
            int c0 = warp_n * 16 + j * 8 + 2 * (lane & 3);
            #pragma unroll
            for (int hrow = 0; hrow < 2; hrow++) {
                int grow = m0 + r + 8 * hrow;
                if (grow >= n_nodes) continue;
                float ns = g_norm_src[grow];
                __half2 v = __floats2half2_rn(acc[i][j][2 * hrow + 0] * ns,
                                              acc[i][j][2 * hrow + 1] * ns);
                *reinterpret_cast<__half2*>(&g_ypre16[(size_t)grow * OUT_DIM + c0]) = v;
            }
        }
    }
}

// ---------------- SpMM2 (CSR by dst, no atomics): out = norm_dst*sum ypre16[src] + b2 ----------------
// warp per dst node; lane covers 2 halves (4B); 8 gathers in flight
__global__ void k_spmm2(float* __restrict__ out, const float* __restrict__ b2, int n_nodes) {
    int node = (blockIdx.x * blockDim.x + threadIdx.x) >> 5;
    if (node >= n_nodes) return;
    int lane = threadIdx.x & 31;
    int e = g_rowptr[node];
    const int end = g_rowptr[node + 1];
    const uint32_t* y1 = reinterpret_cast<const uint32_t*>(g_ypre16);
    float2 acc = make_float2(0.f, 0.f);
    for (; e + 8 <= end; e += 8) {
        int s[8];
        #pragma unroll
        for (int i = 0; i < 8; i++) s[i] = __ldg(&g_esrc[e + i]);
        uint32_t v[8];
        #pragma unroll
        for (int i = 0; i < 8; i++) v[i] = y1[(size_t)s[i] * 32 + lane];
        #pragma unroll
        for (int i = 0; i < 8; i++) {
            __half2 a = *reinterpret_cast<__half2*>(&v[i]);
            float2 fa = __half22float2(a);
            acc.x += fa.x; acc.y += fa.y;
        }
    }
    for (; e < end; e++) {
        int s = __ldg(&g_esrc[e]);
        uint32_t v = y1[(size_t)s * 32 + lane];
        __half2 a = *reinterpret_cast<__half2*>(&v);
        float2 fa = __half22float2(a);
        acc.x += fa.x; acc.y += fa.y;
    }
    float nd = g_norm_dst[node];
    float2 bb = __ldg(&reinterpret_cast<const float2*>(b2)[lane]);
    float2 o;
    o.x = acc.x * nd + bb.x;
    o.y = acc.y * nd + bb.y;
    reinterpret_cast<float2*>(out)[(size_t)node * 32 + lane] = o;
}

// ---------------- launch ----------------
extern "C" void kernel_launch(void* const* d_in, const int* in_sizes, int n_in,
                              void* d_out, int out_size) {
    const float* h  = (const float*)d_in[0];
    const float* W1 = (const float*)d_in[1];
    const float* b1 = (const float*)d_in[2];
    const float* W2 = (const float*)d_in[3];
    const float* b2 = (const float*)d_in[4];
    const float* p  = (const float*)d_in[5];
    const int* src  = (const int*)d_in[6];
    const int* dst  = (const int*)d_in[7];

    const int n_nodes = in_sizes[0] / IN_DIM;   // 100000
    const int n_edges = in_sizes[6];            // 1600000
    float* out = (float*)d_out;

    cudaFuncSetAttribute(k_gemm1, cudaFuncAttributeMaxDynamicSharedMemorySize, SMEM_BYTES);
    cudaFuncSetAttribute(k_gemm2, cudaFuncAttributeMaxDynamicSharedMemorySize, SMEM_BYTES);

    k_zero<<<1024, 256>>>();
    k_degree<<<(n_edges + 1023) / 1024, 256>>>(src, dst, n_edges);
    k_scan<<<1, 1024>>>();
    k_norm<<<(n_nodes + 255) / 256, 256>>>(n_nodes);
    k_scatter<<<(n_edges + 1023) / 1024, 256>>>(src, dst, n_edges);
    k_prep<<<2048, 256>>>(h, W1, W2);

    // SpMM1 (CSR, atomic-free)
    k_spmm1<<<(n_nodes + 7) / 8, 256>>>(n_nodes);
    // GEMM1
    {
        dim3 grid(NN_PAD / BM, HID_DIM / BN);   // 782 x 4
        k_gemm1<<<grid, 256, SMEM_BYTES>>>(b1, p, n_nodes);
    }
    // GEMM2
    {
        dim3 grid(NN_PAD / BM, 1);              // 782
        k_gemm2<<<grid, 256, SMEM_BYTES>>>(n_nodes);
    }
    // SpMM2 (CSR, atomic-free, fused bias+norm)
    k_spmm2<<<(n_nodes + 7) / 8, 256>>>(out, b2, n_nodes);
}

// round 13
// speedup vs baseline: 1.3064x; 1.3064x over previous
#include <cuda_runtime.h>
#include <cuda_bf16.h>
#include <cuda_fp16.h>
#include <stdint.h>

#define NN 100000
#define NN_PAD 100096
#define NE 1600000
#define IN_DIM 128
#define HID_DIM 256
#define OUT_DIM 64

// ---------------- device scratch ----------------
__device__ __align__(16) float g_norm_src[NN_PAD];
__device__ __align__(16) float g_norm_dst[NN_PAD];
__device__ __align__(16) __half g_h16[(size_t)NN * IN_DIM];            // fp16(h * norm_src[row])
__device__ __align__(16) __half g_xagg16[(size_t)NN_PAD * IN_DIM];     // fp16 accumulator (RED target)
__device__ __align__(16) __nv_bfloat16 g_xa_hi[(size_t)NN_PAD * IN_DIM];
__device__ __align__(16) __nv_bfloat16 g_xa_lo[(size_t)NN_PAD * IN_DIM];
__device__ __align__(16) __nv_bfloat16 g_w1t_hi[HID_DIM * IN_DIM];     // [n][k]
__device__ __align__(16) __nv_bfloat16 g_w1t_lo[HID_DIM * IN_DIM];
__device__ __align__(16) __nv_bfloat16 g_w2t_hi[OUT_DIM * HID_DIM];    // [n][k]
__device__ __align__(16) __nv_bfloat16 g_w2t_lo[OUT_DIM * HID_DIM];
__device__ __align__(16) __nv_bfloat16 g_hid_hi[(size_t)NN_PAD * HID_DIM];
__device__ __align__(16) __nv_bfloat16 g_hid_lo[(size_t)NN_PAD * HID_DIM];
__device__ __align__(16) __half g_ypre16[(size_t)NN * OUT_DIM];

__device__ __forceinline__ void split_bf16(float v, __nv_bfloat16& hi, __nv_bfloat16& lo) {
    hi = __float2bfloat16(v);
    lo = __float2bfloat16(v - __bfloat162float(hi));
}

#define MMA_BF16(d, a, b0, b1)                                                  \
    asm volatile("mma.sync.aligned.m16n8k16.row.col.f32.bf16.bf16.f32 "         \
                 "{%0,%1,%2,%3}, {%4,%5,%6,%7}, {%8,%9}, {%0,%1,%2,%3};"        \
                 : "+f"(d[0]), "+f"(d[1]), "+f"(d[2]), "+f"(d[3])               \
                 : "r"(a[0]), "r"(a[1]), "r"(a[2]), "r"(a[3]), "r"(b0), "r"(b1))

__device__ __forceinline__ void cp16(void* smem_dst, const void* gmem_src) {
    uint32_t s = (uint32_t)__cvta_generic_to_shared(smem_dst);
    asm volatile("cp.async.cg.shared.global [%0], [%1], 16;" :: "r"(s), "l"(gmem_src) : "memory");
}
#define CP_COMMIT() asm volatile("cp.async.commit_group;" ::: "memory")
#define CP_WAIT(n)  asm volatile("cp.async.wait_group %0;" :: "n"(n) : "memory")

// ---------------- zero init + out=b2 ----------------
__global__ void k_zero(const float* __restrict__ b2, float4* __restrict__ dout4, int n_nodes) {
    int i = blockIdx.x * blockDim.x + threadIdx.x;
    int stride = gridDim.x * blockDim.x;
    // zero fp16 xagg accumulator (NN_PAD * 128 halves = uint4 chunks)
    const int nxa = NN_PAD * (IN_DIM / 8);
    uint4* xa = reinterpret_cast<uint4*>(g_xagg16);
    const uint4 z4 = make_uint4(0u, 0u, 0u, 0u);
    for (int j = i; j < nxa; j += stride) xa[j] = z4;
    // out rows = b2 (RED target; bias pre-applied)
    const float4* b24 = reinterpret_cast<const float4*>(b2);
    const int no4 = n_nodes * (OUT_DIM / 4);
    for (int j = i; j < no4; j += stride) dout4[j] = b24[j & 15];
    for (int j = i; j < NN_PAD; j += stride) { g_norm_src[j] = 0.f; g_norm_dst[j] = 0.f; }
    // hid pad rows (read by gemm2 A tiles) must be zero
    const int hid_pad = (NN_PAD - NN) * (HID_DIM / 8);
    uint4* hh = reinterpret_cast<uint4*>(g_hid_hi + (size_t)NN * HID_DIM);
    uint4* hl = reinterpret_cast<uint4*>(g_hid_lo + (size_t)NN * HID_DIM);
    for (int j = i; j < hid_pad; j += stride) { hh[j] = z4; hl[j] = z4; }
}

// ---------------- degrees ----------------
__global__ void k_degree(const int* __restrict__ src, const int* __restrict__ dst, int n_edges) {
    int i = blockIdx.x * blockDim.x + threadIdx.x;
    int stride = gridDim.x * blockDim.x;
    for (int e = i; e < n_edges; e += stride) {
        atomicAdd(&g_norm_src[src[e]], 1.0f);
        atomicAdd(&g_norm_dst[dst[e]], 1.0f);
    }
}

__global__ void k_norm(int n_nodes) {
    int i = blockIdx.x * blockDim.x + threadIdx.x;
    if (i < n_nodes) {
        g_norm_src[i] = rsqrtf(fmaxf(g_norm_src[i], 1.0f));
        g_norm_dst[i] = rsqrtf(fmaxf(g_norm_dst[i], 1.0f));
    }
}

// ---------------- prep: h16 = fp16(h * norm_src[row]); split+transpose weights ----------------
__global__ void k_prep(const float* __restrict__ h,
                       const float* __restrict__ W1, const float* __restrict__ W2) {
    int i = blockIdx.x * blockDim.x + threadIdx.x;
    int stride = gridDim.x * blockDim.x;
    const int n1 = HID_DIM * IN_DIM;
    const int n2 = OUT_DIM * HID_DIM;
    for (int j = i; j < n1 + n2; j += stride) {
        if (j < n1) {
            int n = j / IN_DIM, k = j % IN_DIM;
            float v = W1[(size_t)k * HID_DIM + n];
            __nv_bfloat16 hi, lo;
            split_bf16(v, hi, lo);
            g_w1t_hi[j] = hi; g_w1t_lo[j] = lo;
        } else {
            int jj = j - n1;
            int n = jj / HID_DIM, k = jj % HID_DIM;
            float v = W2[(size_t)k * OUT_DIM + n];
            __nv_bfloat16 hi, lo;
            split_bf16(v, hi, lo);
            g_w2t_hi[jj] = hi; g_w2t_lo[jj] = lo;
        }
    }
    const int nh4 = NN * (IN_DIM / 4);
    for (int j = i; j < nh4; j += stride) {
        int row = j >> 5;
        float ns = g_norm_src[row];
        float4 v = reinterpret_cast<const float4*>(h)[j];
        __half2 a = __floats2half2_rn(v.x * ns, v.y * ns);
        __half2 b = __floats2half2_rn(v.z * ns, v.w * ns);
        uint2 pk;
        pk.x = *reinterpret_cast<uint32_t*>(&a);
        pk.y = *reinterpret_cast<uint32_t*>(&b);
        reinterpret_cast<uint2*>(g_h16)[j] = pk;
    }
}

// ---------------- SpMM1: xagg16[dst] += h16[src]  (fp16x2 REDs, norm_src pre-folded) ----------------
// half-warp per edge (16 lanes x uint4 = 256B row), 8 edges/warp, MLP=4
__global__ void k_spmm1(const int* __restrict__ src, const int* __restrict__ dst,
                        int n_edges) {
    int w = (blockIdx.x * blockDim.x + threadIdx.x) >> 5;
    int lane = threadIdx.x & 31;
    int half_id = lane >> 4;
    int l = lane & 15;
    int e0 = w * 8;
    if (e0 >= n_edges) return;
    int s[4], d[4];
    #pragma unroll
    for (int i = 0; i < 4; i++) {
        int e = min(e0 + 2 * i + half_id, n_edges - 1);
        s[i] = __ldg(&src[e]);
        d[i] = __ldg(&dst[e]);
    }
    uint4 v[4];
    #pragma unroll
    for (int i = 0; i < 4; i++)
        v[i] = reinterpret_cast<const uint4*>(g_h16 + (size_t)s[i] * IN_DIM)[l];
    #pragma unroll
    for (int i = 0; i < 4; i++) {
        if (e0 + 2 * i + half_id >= n_edges) break;
        uint4* orow = reinterpret_cast<uint4*>(g_xagg16 + (size_t)d[i] * IN_DIM);
        asm volatile("red.global.add.noftz.v4.f16x2 [%0], {%1,%2,%3,%4};"
                     :: "l"(orow + l), "r"(v[i].x), "r"(v[i].y), "r"(v[i].z), "r"(v[i].w)
                     : "memory");
    }
}

// ---------------- split pass: xa = split(fp32(xagg16) * norm_dst) ----------------
__global__ void k_split() {
    int i = blockIdx.x * blockDim.x + threadIdx.x;
    int stride = gridDim.x * blockDim.x;
    const int total = NN_PAD * (IN_DIM / 8);   // uint4 = 8 halves
    for (int j = i; j < total; j += stride) {
        int row = j >> 4;   // 16 uint4 per row
        float nd = g_norm_dst[row];
        uint4 v = reinterpret_cast<const uint4*>(g_xagg16)[j];
        float2 f0 = __half22float2(*reinterpret_cast<__half2*>(&v.x));
        float2 f1 = __half22float2(*reinterpret_cast<__half2*>(&v.y));
        float2 f2 = __half22float2(*reinterpret_cast<__half2*>(&v.z));
        float2 f3 = __half22float2(*reinterpret_cast<__half2*>(&v.w));
        float x[8] = {f0.x * nd, f0.y * nd, f1.x * nd, f1.y * nd,
                      f2.x * nd, f2.y * nd, f3.x * nd, f3.y * nd};
        uint4 ph, pl;
        uint32_t* php = reinterpret_cast<uint32_t*>(&ph);
        uint32_t* plp = reinterpret_cast<uint32_t*>(&pl);
        #pragma unroll
        for (int q = 0; q < 4; q++) {
            __nv_bfloat16 h0, l0, h1, l1;
            split_bf16(x[2 * q], h0, l0);
            split_bf16(x[2 * q + 1], h1, l1);
            __nv_bfloat162 th(h0, h1), tl(l0, l1);
            php[q] = *reinterpret_cast<uint32_t*>(&th);
            plp[q] = *reinterpret_cast<uint32_t*>(&tl);
        }
        reinterpret_cast<uint4*>(g_xa_hi)[j] = ph;
        reinterpret_cast<uint4*>(g_xa_lo)[j] = pl;
    }
}

// ---------------- GEMM tiles ----------------
#define BM 128
#define BN 64
#define BK 32
#define KPAD 40
#define STAGE_ELEMS 15360
#define SMEM_BYTES (2 * STAGE_ELEMS * 2)

// GEMM1: hidden = relu(xa @ W1 + b1) * clip(p,0,1); cp.async double-buffered
__global__ __launch_bounds__(256) void k_gemm1(const float* __restrict__ b1,
                                               const float* __restrict__ p,
                                               int n_nodes) {
    extern __shared__ __nv_bfloat16 smem[];
    const int m0 = blockIdx.x * BM;
    const int n0 = blockIdx.y * BN;
    const int tid = threadIdx.x;
    const int lane = tid & 31;
    const int wid = tid >> 5;
    const int warp_m = wid >> 2;
    const int warp_n = wid & 3;
    const int bn = tid >> 2;
    const int bq = tid & 3;

    auto load_stage = [&](int s, int k0) {
        __nv_bfloat16* As_hi = smem + s * STAGE_ELEMS;
        __nv_bfloat16* As_lo = As_hi + 5120;
        __nv_bfloat16* Bs_hi = As_hi + 10240;
        __nv_bfloat16* Bs_lo = As_hi + 12800;
        #pragma unroll
        for (int i = 0; i < 2; i++) {
            int idx = tid + 256 * i;
            int row = idx >> 2;
            int q = idx & 3;
            cp16(&As_hi[row * KPAD + 8 * q], &g_xa_hi[(size_t)(m0 + row) * IN_DIM + k0 + 8 * q]);
            cp16(&As_lo[row * KPAD + 8 * q], &g_xa_lo[(size_t)(m0 + row) * IN_DIM + k0 + 8 * q]);
        }
        cp16(&Bs_hi[bn * KPAD + 8 * bq], &g_w1t_hi[(size_t)(n0 + bn) * IN_DIM + k0 + 8 * bq]);
        cp16(&Bs_lo[bn * KPAD + 8 * bq], &g_w1t_lo[(size_t)(n0 + bn) * IN_DIM + k0 + 8 * bq]);
        CP_COMMIT();
    };

    float acc[4][2][4];
    #pragma unroll
    for (int i = 0; i < 4; i++)
        #pragma unroll
        for (int j = 0; j < 2; j++)
            #pragma unroll
            for (int q = 0; q < 4; q++) acc[i][j][q] = 0.f;

    const int K_ITERS = IN_DIM / BK;
    load_stage(0, 0);
    for (int it = 0; it < K_ITERS; it++) {
        if (it + 1 < K_ITERS) {
            load_stage((it + 1) & 1, (it + 1) * BK);
            CP_WAIT(1);
        } else {
            CP_WAIT(0);
        }
        __syncthreads();

        __nv_bfloat16* As_hi = smem + (it & 1) * STAGE_ELEMS;
        __nv_bfloat16* As_lo = As_hi + 5120;
        __nv_bfloat16* Bs_hi = As_hi + 10240;
        __nv_bfloat16* Bs_lo = As_hi + 12800;

        #pragma unroll
        for (int ks = 0; ks < 2; ks++) {
            const int kc = ks * 16 + 2 * (lane & 3);
            uint32_t ah[4][4], al[4][4];
            #pragma unroll
            for (int i = 0; i < 4; i++) {
                int r = warp_m * 64 + i * 16 + (lane >> 2);
                ah[i][0] = *reinterpret_cast<uint32_t*>(&As_hi[r * KPAD + kc]);
                ah[i][1] = *reinterpret_cast<uint32_t*>(&As_hi[(r + 8) * KPAD + kc]);
                ah[i][2] = *reinterpret_cast<uint32_t*>(&As_hi[r * KPAD + kc + 8]);
                ah[i][3] = *reinterpret_cast<uint32_t*>(&As_hi[(r + 8) * KPAD + kc + 8]);
                al[i][0] = *reinterpret_cast<uint32_t*>(&As_lo[r * KPAD + kc]);
                al[i][1] = *reinterpret_cast<uint32_t*>(&As_lo[(r + 8) * KPAD + kc]);
                al[i][2] = *reinterpret_cast<uint32_t*>(&As_lo[r * KPAD + kc + 8]);
                al[i][3] = *reinterpret_cast<uint32_t*>(&As_lo[(r + 8) * KPAD + kc + 8]);
            }
            #pragma unroll
            for (int j = 0; j < 2; j++) {
                int c = warp_n * 16 + j * 8 + (lane >> 2);
                uint32_t bh0 = *reinterpret_cast<uint32_t*>(&Bs_hi[c * KPAD + kc]);
                uint32_t bh1 = *reinterpret_cast<uint32_t*>(&Bs_hi[c * KPAD + kc + 8]);
                uint32_t bl0 = *reinterpret_cast<uint32_t*>(&Bs_lo[c * KPAD + kc]);
                uint32_t bl1 = *reinterpret_cast<uint32_t*>(&Bs_lo[c * KPAD + kc + 8]);
                #pragma unroll
                for (int i = 0; i < 4; i++) {
                    MMA_BF16(acc[i][j], ah[i], bh0, bh1);
                    MMA_BF16(acc[i][j], ah[i], bl0, bl1);
                    MMA_BF16(acc[i][j], al[i], bh0, bh1);
                }
            }
        }
        __syncthreads();
    }

    #pragma unroll
    for (int i = 0; i < 4; i++) {
        int r = warp_m * 64 + i * 16 + (lane >> 2);
        #pragma unroll
        for (int j = 0; j < 2; j++) {
            int c0 = n0 + warp_n * 16 + j * 8 + 2 * (lane & 3);
            float bb0 = b1[c0], bb1 = b1[c0 + 1];
            float p0 = fminf(fmaxf(p[c0], 0.f), 1.f);
            float p1 = fminf(fmaxf(p[c0 + 1], 0.f), 1.f);
            #pragma unroll
            for (int hrow = 0; hrow < 2; hrow++) {
                int grow = m0 + r + 8 * hrow;
                if (grow >= n_nodes) continue;
                float v0 = fmaxf(acc[i][j][2 * hrow + 0] + bb0, 0.f) * p0;
                float v1 = fmaxf(acc[i][j][2 * hrow + 1] + bb1, 0.f) * p1;
                __nv_bfloat16 h0, l0, h1, l1;
                split_bf16(v0, h0, l0);
                split_bf16(v1, h1, l1);
                *reinterpret_cast<__nv_bfloat162*>(&g_hid_hi[(size_t)grow * HID_DIM + c0]) = __nv_bfloat162(h0, h1);
                *reinterpret_cast<__nv_bfloat162*>(&g_hid_lo[(size_t)grow * HID_DIM + c0]) = __nv_bfloat162(l0, l1);
            }
        }
    }
}

// GEMM2: ypre16 = fp16((hidden @ W2) * norm_src[row]); cp.async double-buffered
__global__ __launch_bounds__(256) void k_gemm2(int n_nodes) {
    extern __shared__ __nv_bfloat16 smem[];
    const int m0 = blockIdx.x * BM;
    const int tid = threadIdx.x;
    const int lane = tid & 31;
    const int wid = tid >> 5;
    const int warp_m = wid >> 2;
    const int warp_n = wid & 3;
    const int bn = tid >> 2;
    const int bq = tid & 3;

    auto load_stage = [&](int s, int k0) {
        __nv_bfloat16* As_hi = smem + s * STAGE_ELEMS;
        __nv_bfloat16* As_lo = As_hi + 5120;
        __nv_bfloat16* Bs_hi = As_hi + 10240;
        __nv_bfloat16* Bs_lo = As_hi + 12800;
        #pragma unroll
        for (int i = 0; i < 2; i++) {
            int idx = tid + 256 * i;
            int row = idx >> 2;
            int q = idx & 3;
            cp16(&As_hi[row * KPAD + 8 * q], &g_hid_hi[(size_t)(m0 + row) * HID_DIM + k0 + 8 * q]);
            cp16(&As_lo[row * KPAD + 8 * q], &g_hid_lo[(size_t)(m0 + row) * HID_DIM + k0 + 8 * q]);
        }
        cp16(&Bs_hi[bn * KPAD + 8 * bq], &g_w2t_hi[(size_t)bn * HID_DIM + k0 + 8 * bq]);
        cp16(&Bs_lo[bn * KPAD + 8 * bq], &g_w2t_lo[(size_t)bn * HID_DIM + k0 + 8 * bq]);
        CP_COMMIT();
    };

    float acc[4][2][4];
    #pragma unroll
    for (int i = 0; i < 4; i++)
        #pragma unroll
        for (int j = 0; j < 2; j++)
            #pragma unroll
            for (int q = 0; q < 4; q++) acc[i][j][q] = 0.f;

    const int K_ITERS = HID_DIM / BK;
    load_stage(0, 0);
    for (int it = 0; it < K_ITERS; it++) {
        if (it + 1 < K_ITERS) {
            load_stage((it + 1) & 1, (it + 1) * BK);
            CP_WAIT(1);
        } else {
            CP_WAIT(0);
        }
        __syncthreads();

        __nv_bfloat16* As_hi = smem + (it & 1) * STAGE_ELEMS;
        __nv_bfloat16* As_lo = As_hi + 5120;
        __nv_bfloat16* Bs_hi = As_hi + 10240;
        __nv_bfloat16* Bs_lo = As_hi + 12800;

        #pragma unroll
        for (int ks = 0; ks < 2; ks++) {
            const int kc = ks * 16 + 2 * (lane & 3);
            uint32_t ah[4][4], al[4][4];
            #pragma unroll
            for (int i = 0; i < 4; i++) {
                int r = warp_m * 64 + i * 16 + (lane >> 2);
                ah[i][0] = *reinterpret_cast<uint32_t*>(&As_hi[r * KPAD + kc]);
                ah[i][1] = *reinterpret_cast<uint32_t*>(&As_hi[(r + 8) * KPAD + kc]);
                ah[i][2] = *reinterpret_cast<uint32_t*>(&As_hi[r * KPAD + kc + 8]);
                ah[i][3] = *reinterpret_cast<uint32_t*>(&As_hi[(r + 8) * KPAD + kc + 8]);
                al[i][0] = *reinterpret_cast<uint32_t*>(&As_lo[r * KPAD + kc]);
                al[i][1] = *reinterpret_cast<uint32_t*>(&As_lo[(r + 8) * KPAD + kc]);
                al[i][2] = *reinterpret_cast<uint32_t*>(&As_lo[r * KPAD + kc + 8]);
                al[i][3] = *reinterpret_cast<uint32_t*>(&As_lo[(r + 8) * KPAD + kc + 8]);
            }
            #pragma unroll
            for (int j = 0; j < 2; j++) {
                int c = warp_n * 16 + j * 8 + (lane >> 2);
                uint32_t bh0 = *reinterpret_cast<uint32_t*>(&Bs_hi[c * KPAD + kc]);
                uint32_t bh1 = *reinterpret_cast<uint32_t*>(&Bs_hi[c * KPAD + kc + 8]);
                uint32_t bl0 = *reinterpret_cast<uint32_t*>(&Bs_lo[c * KPAD + kc]);
                uint32_t bl1 = *reinterpret_cast<uint32_t*>(&Bs_lo[c * KPAD + kc + 8]);
                #pragma unroll
                for (int i = 0; i < 4; i++) {
                    MMA_BF16(acc[i][j], ah[i], bh0, bh1);
                    MMA_BF16(acc[i][j], ah[i], bl0, bl1);
                    MMA_BF16(acc[i][j], al[i], bh0, bh1);
                }
            }
        }
        __syncthreads();
    }

    #pragma unroll
    for (int i = 0; i < 4; i++) {
        int r = warp_m * 64 + i * 16 + (lane >> 2);
        #pragma unroll
        for (int j = 0; j < 2; j++) {
            int c0 = warp_n * 16 + j * 8 + 2 * (lane & 3);
            #pragma unroll
            for (int hrow = 0; hrow < 2; hrow++) {
                int grow = m0 + r + 8 * hrow;
                if (grow >= n_nodes) continue;
                float ns = g_norm_src[grow];
                __half2 v = __floats2half2_rn(acc[i][j][2 * hrow + 0] * ns,
                                              acc[i][j][2 * hrow + 1] * ns);
                *reinterpret_cast<__half2*>(&g_ypre16[(size_t)grow * OUT_DIM + c0]) = v;
            }
        }
    }
}

// ---------------- SpMM2 (fused final): out[dst] += ypre16[src]*norm_dst[dst]; out pre-init b2 ----------------
__global__ void k_spmm2(const int* __restrict__ src, const int* __restrict__ dst,
                        float* __restrict__ out, int n_edges) {
    int w = (blockIdx.x * blockDim.x + threadIdx.x) >> 5;
    int lane = threadIdx.x & 31;
    int half = lane >> 4;
    int l = lane & 15;
    int e0 = w * 8;
    if (e0 >= n_edges) return;
    int s[4], d[4];
    #pragma unroll
    for (int i = 0; i < 4; i++) {
        int e = min(e0 + 2 * i + half, n_edges - 1);
        s[i] = __ldg(&src[e]);
        d[i] = __ldg(&dst[e]);
    }
    float nd[4];
    #pragma unroll
    for (int i = 0; i < 4; i++) nd[i] = g_norm_dst[d[i]];
    uint2 v[4];
    #pragma unroll
    for (int i = 0; i < 4; i++)
        v[i] = reinterpret_cast<const uint2*>(g_ypre16 + (size_t)s[i] * OUT_DIM)[l];
    #pragma unroll
    for (int i = 0; i < 4; i++) {
        if (e0 + 2 * i + half >= n_edges) break;
        __half2 a = *reinterpret_cast<__half2*>(&v[i].x);
        __half2 b = *reinterpret_cast<__half2*>(&v[i].y);
        float2 fa = __half22float2(a);
        float2 fb = __half22float2(b);
        float4 t;
        t.x = fa.x * nd[i]; t.y = fa.y * nd[i];
        t.z = fb.x * nd[i]; t.w = fb.y * nd[i];
        float4* orow = reinterpret_cast<float4*>(out + (size_t)d[i] * OUT_DIM);
        asm volatile("red.global.add.v4.f32 [%0], {%1,%2,%3,%4};"
                     :: "l"(orow + l), "f"(t.x), "f"(t.y), "f"(t.z), "f"(t.w)
                     : "memory");
    }
}

// ---------------- launch ----------------
extern "C" void kernel_launch(void* const* d_in, const int* in_sizes, int n_in,
                              void* d_out, int out_size) {
    const float* h  = (const float*)d_in[0];
    const float* W1 = (const float*)d_in[1];
    const float* b1 = (const float*)d_in[2];
    const float* W2 = (const float*)d_in[3];
    const float* b2 = (const float*)d_in[4];
    const float* p  = (const float*)d_in[5];
    const int* src  = (const int*)d_in[6];
    const int* dst  = (const int*)d_in[7];

    const int n_nodes = in_sizes[0] / IN_DIM;   // 100000
    const int n_edges = in_sizes[6];            // 1600000
    float* out = (float*)d_out;

    cudaFuncSetAttribute(k_gemm1, cudaFuncAttributeMaxDynamicSharedMemorySize, SMEM_BYTES);
    cudaFuncSetAttribute(k_gemm2, cudaFuncAttributeMaxDynamicSharedMemorySize, SMEM_BYTES);

    k_zero<<<2048, 256>>>(b2, reinterpret_cast<float4*>(out), n_nodes);
    k_degree<<<(n_edges + 255) / 256, 256>>>(src, dst, n_edges);
    k_norm<<<(n_nodes + 255) / 256, 256>>>(n_nodes);
    k_prep<<<2048, 256>>>(h, W1, W2);

    // SpMM1: fp16x2 REDs, 8 edges/warp (half-warp per edge)
    {
        int warps = (n_edges + 7) / 8;
        k_spmm1<<<(warps + 7) / 8, 256>>>(src, dst, n_edges);
    }
    // split: fp16 xagg * norm_dst -> bf16 hi/lo
    k_split<<<2048, 256>>>();
    // GEMM1
    {
        dim3 grid(NN_PAD / BM, HID_DIM / BN);   // 782 x 4
        k_gemm1<<<grid, 256, SMEM_BYTES>>>(b1, p, n_nodes);
    }
    // GEMM2
    {
        dim3 grid(NN_PAD / BM, 1);              // 782
        k_gemm2<<<grid, 256, SMEM_BYTES>>>(n_nodes);
    }
    // SpMM2: fp16 gather, fp32 RED, fused norm_dst + bias
    {
        int warps = (n_edges + 7) / 8;
        k_spmm2<<<(warps + 7) / 8, 256>>>(src, dst, out, n_edges);
    }
}

// round 14
// speedup vs baseline: 1.3912x; 1.0649x over previous
#include <cuda_runtime.h>
#include <cuda_bf16.h>
#include <cuda_fp16.h>
#include <stdint.h>

#define NN 100000
#define NN_PAD 100096
#define NE 1600000
#define IN_DIM 128
#define HID_DIM 256
#define OUT_DIM 64

// ---------------- device scratch ----------------
__device__ __align__(16) float g_norm_src[NN_PAD];
__device__ __align__(16) float g_norm_dst[NN_PAD];
__device__ __align__(16) __half g_h16[(size_t)NN * IN_DIM];            // fp16(h * norm_src[row])
__device__ __align__(16) __half g_xagg16[(size_t)NN_PAD * IN_DIM];     // fp16 accumulator (RED target)
__device__ __align__(16) __half g_out16[(size_t)NN * OUT_DIM];         // fp16 output accumulator
__device__ __align__(16) __nv_bfloat16 g_xa_hi[(size_t)NN_PAD * IN_DIM];
__device__ __align__(16) __nv_bfloat16 g_xa_lo[(size_t)NN_PAD * IN_DIM];
__device__ __align__(16) __nv_bfloat16 g_w1t_hi[HID_DIM * IN_DIM];     // [n][k]
__device__ __align__(16) __nv_bfloat16 g_w1t_lo[HID_DIM * IN_DIM];
__device__ __align__(16) __nv_bfloat16 g_w2t_hi[OUT_DIM * HID_DIM];    // [n][k]
__device__ __align__(16) __nv_bfloat16 g_w2t_lo[OUT_DIM * HID_DIM];
__device__ __align__(16) __nv_bfloat16 g_hid_hi[(size_t)NN_PAD * HID_DIM];
__device__ __align__(16) __nv_bfloat16 g_hid_lo[(size_t)NN_PAD * HID_DIM];
__device__ __align__(16) __half g_ypre16[(size_t)NN * OUT_DIM];

__device__ __forceinline__ void split_bf16(float v, __nv_bfloat16& hi, __nv_bfloat16& lo) {
    hi = __float2bfloat16(v);
    lo = __float2bfloat16(v - __bfloat162float(hi));
}

#define MMA_BF16(d, a, b0, b1)                                                  \
    asm volatile("mma.sync.aligned.m16n8k16.row.col.f32.bf16.bf16.f32 "         \
                 "{%0,%1,%2,%3}, {%4,%5,%6,%7}, {%8,%9}, {%0,%1,%2,%3};"        \
                 : "+f"(d[0]), "+f"(d[1]), "+f"(d[2]), "+f"(d[3])               \
                 : "r"(a[0]), "r"(a[1]), "r"(a[2]), "r"(a[3]), "r"(b0), "r"(b1))

__device__ __forceinline__ void cp16(void* smem_dst, const void* gmem_src) {
    uint32_t s = (uint32_t)__cvta_generic_to_shared(smem_dst);
    asm volatile("cp.async.cg.shared.global [%0], [%1], 16;" :: "r"(s), "l"(gmem_src) : "memory");
}
#define CP_COMMIT() asm volatile("cp.async.commit_group;" ::: "memory")
#define CP_WAIT(n)  asm volatile("cp.async.wait_group %0;" :: "n"(n) : "memory")

// ---------------- zero init ----------------
__global__ void k_zero() {
    int i = blockIdx.x * blockDim.x + threadIdx.x;
    int stride = gridDim.x * blockDim.x;
    const uint4 z4 = make_uint4(0u, 0u, 0u, 0u);
    // zero fp16 xagg accumulator
    const int nxa = NN_PAD * (IN_DIM / 8);
    uint4* xa = reinterpret_cast<uint4*>(g_xagg16);
    for (int j = i; j < nxa; j += stride) xa[j] = z4;
    // zero fp16 out accumulator
    const int nout = NN * (OUT_DIM / 8);
    uint4* o16 = reinterpret_cast<uint4*>(g_out16);
    for (int j = i; j < nout; j += stride) o16[j] = z4;
    for (int j = i; j < NN_PAD; j += stride) { g_norm_src[j] = 0.f; g_norm_dst[j] = 0.f; }
    // hid pad rows (read by gemm2 A tiles) must be zero
    const int hid_pad = (NN_PAD - NN) * (HID_DIM / 8);
    uint4* hh = reinterpret_cast<uint4*>(g_hid_hi + (size_t)NN * HID_DIM);
    uint4* hl = reinterpret_cast<uint4*>(g_hid_lo + (size_t)NN * HID_DIM);
    for (int j = i; j < hid_pad; j += stride) { hh[j] = z4; hl[j] = z4; }
}

// ---------------- degrees ----------------
__global__ void k_degree(const int* __restrict__ src, const int* __restrict__ dst, int n_edges) {
    int i = blockIdx.x * blockDim.x + threadIdx.x;
    int stride = gridDim.x * blockDim.x;
    for (int e = i; e < n_edges; e += stride) {
        atomicAdd(&g_norm_src[src[e]], 1.0f);
        atomicAdd(&g_norm_dst[dst[e]], 1.0f);
    }
}

__global__ void k_norm(int n_nodes) {
    int i = blockIdx.x * blockDim.x + threadIdx.x;
    if (i < n_nodes) {
        g_norm_src[i] = rsqrtf(fmaxf(g_norm_src[i], 1.0f));
        g_norm_dst[i] = rsqrtf(fmaxf(g_norm_dst[i], 1.0f));
    }
}

// ---------------- prep: h16 = fp16(h * norm_src[row]); split+transpose weights ----------------
__global__ void k_prep(const float* __restrict__ h,
                       const float* __restrict__ W1, const float* __restrict__ W2) {
    int i = blockIdx.x * blockDim.x + threadIdx.x;
    int stride = gridDim.x * blockDim.x;
    const int n1 = HID_DIM * IN_DIM;
    const int n2 = OUT_DIM * HID_DIM;
    for (int j = i; j < n1 + n2; j += stride) {
        if (j < n1) {
            int n = j / IN_DIM, k = j % IN_DIM;
            float v = W1[(size_t)k * HID_DIM + n];
            __nv_bfloat16 hi, lo;
            split_bf16(v, hi, lo);
            g_w1t_hi[j] = hi; g_w1t_lo[j] = lo;
        } else {
            int jj = j - n1;
            int n = jj / HID_DIM, k = jj % HID_DIM;
            float v = W2[(size_t)k * OUT_DIM + n];
            __nv_bfloat16 hi, lo;
            split_bf16(v, hi, lo);
            g_w2t_hi[jj] = hi; g_w2t_lo[jj] = lo;
        }
    }
    const int nh4 = NN * (IN_DIM / 4);
    for (int j = i; j < nh4; j += stride) {
        int row = j >> 5;
        float ns = g_norm_src[row];
        float4 v = reinterpret_cast<const float4*>(h)[j];
        __half2 a = __floats2half2_rn(v.x * ns, v.y * ns);
        __half2 b = __floats2half2_rn(v.z * ns, v.w * ns);
        uint2 pk;
        pk.x = *reinterpret_cast<uint32_t*>(&a);
        pk.y = *reinterpret_cast<uint32_t*>(&b);
        reinterpret_cast<uint2*>(g_h16)[j] = pk;
    }
}

// ---------------- SpMM1: xagg16[dst] += h16[src]  (fp16x2 REDs) ----------------
// half-warp per edge (16 lanes x uint4 = 256B row), 8 edges/warp
__global__ void k_spmm1(const int* __restrict__ src, const int* __restrict__ dst,
                        int n_edges) {
    int w = (blockIdx.x * blockDim.x + threadIdx.x) >> 5;
    int lane = threadIdx.x & 31;
    int half_id = lane >> 4;
    int l = lane & 15;
    int e0 = w * 8;
    if (e0 >= n_edges) return;
    int s[4], d[4];
    #pragma unroll
    for (int i = 0; i < 4; i++) {
        int e = min(e0 + 2 * i + half_id, n_edges - 1);
        s[i] = __ldg(&src[e]);
        d[i] = __ldg(&dst[e]);
    }
    uint4 v[4];
    #pragma unroll
    for (int i = 0; i < 4; i++)
        v[i] = reinterpret_cast<const uint4*>(g_h16 + (size_t)s[i] * IN_DIM)[l];
    #pragma unroll
    for (int i = 0; i < 4; i++) {
        if (e0 + 2 * i + half_id >= n_edges) break;
        uint4* orow = reinterpret_cast<uint4*>(g_xagg16 + (size_t)d[i] * IN_DIM);
        asm volatile("red.global.add.noftz.v4.f16x2 [%0], {%1,%2,%3,%4};"
                     :: "l"(orow + l), "r"(v[i].x), "r"(v[i].y), "r"(v[i].z), "r"(v[i].w)
                     : "memory");
    }
}

// ---------------- split pass: xa = split(fp32(xagg16) * norm_dst) ----------------
__global__ void k_split() {
    int i = blockIdx.x * blockDim.x + threadIdx.x;
    int stride = gridDim.x * blockDim.x;
    const int total = NN_PAD * (IN_DIM / 8);
    for (int j = i; j < total; j += stride) {
        int row = j >> 4;
        float nd = g_norm_dst[row];
        uint4 v = reinterpret_cast<const uint4*>(g_xagg16)[j];
        float2 f0 = __half22float2(*reinterpret_cast<__half2*>(&v.x));
        float2 f1 = __half22float2(*reinterpret_cast<__half2*>(&v.y));
        float2 f2 = __half22float2(*reinterpret_cast<__half2*>(&v.z));
        float2 f3 = __half22float2(*reinterpret_cast<__half2*>(&v.w));
        float x[8] = {f0.x * nd, f0.y * nd, f1.x * nd, f1.y * nd,
                      f2.x * nd, f2.y * nd, f3.x * nd, f3.y * nd};
        uint4 ph, pl;
        uint32_t* php = reinterpret_cast<uint32_t*>(&ph);
        uint32_t* plp = reinterpret_cast<uint32_t*>(&pl);
        #pragma unroll
        for (int q = 0; q < 4; q++) {
            __nv_bfloat16 h0, l0, h1, l1;
            split_bf16(x[2 * q], h0, l0);
            split_bf16(x[2 * q + 1], h1, l1);
            __nv_bfloat162 th(h0, h1), tl(l0, l1);
            php[q] = *reinterpret_cast<uint32_t*>(&th);
            plp[q] = *reinterpret_cast<uint32_t*>(&tl);
        }
        reinterpret_cast<uint4*>(g_xa_hi)[j] = ph;
        reinterpret_cast<uint4*>(g_xa_lo)[j] = pl;
    }
}

// ---------------- GEMM tiles ----------------
#define BM 128
#define BN 64
#define BK 32
#define KPAD 40
#define STAGE_ELEMS 15360
#define SMEM_BYTES (2 * STAGE_ELEMS * 2)

// GEMM1: hidden = relu(xa @ W1 + b1) * clip(p,0,1); cp.async double-buffered
__global__ __launch_bounds__(256) void k_gemm1(const float* __restrict__ b1,
                                               const float* __restrict__ p,
                                               int n_nodes) {
    extern __shared__ __nv_bfloat16 smem[];
    const int m0 = blockIdx.x * BM;
    const int n0 = blockIdx.y * BN;
    const int tid = threadIdx.x;
    const int lane = tid & 31;
    const int wid = tid >> 5;
    const int warp_m = wid >> 2;
    const int warp_n = wid & 3;
    const int bn = tid >> 2;
    const int bq = tid & 3;

    auto load_stage = [&](int s, int k0) {
        __nv_bfloat16* As_hi = smem + s * STAGE_ELEMS;
        __nv_bfloat16* As_lo = As_hi + 5120;
        __nv_bfloat16* Bs_hi = As_hi + 10240;
        __nv_bfloat16* Bs_lo = As_hi + 12800;
        #pragma unroll
        for (int i = 0; i < 2; i++) {
            int idx = tid + 256 * i;
            int row = idx >> 2;
            int q = idx & 3;
            cp16(&As_hi[row * KPAD + 8 * q], &g_xa_hi[(size_t)(m0 + row) * IN_DIM + k0 + 8 * q]);
            cp16(&As_lo[row * KPAD + 8 * q], &g_xa_lo[(size_t)(m0 + row) * IN_DIM + k0 + 8 * q]);
        }
        cp16(&Bs_hi[bn * KPAD + 8 * bq], &g_w1t_hi[(size_t)(n0 + bn) * IN_DIM + k0 + 8 * bq]);
        cp16(&Bs_lo[bn * KPAD + 8 * bq], &g_w1t_lo[(size_t)(n0 + bn) * IN_DIM + k0 + 8 * bq]);
        CP_COMMIT();
    };

    float acc[4][2][4];
    #pragma unroll
    for (int i = 0; i < 4; i++)
        #pragma unroll
        for (int j = 0; j < 2; j++)
            #pragma unroll
            for (int q = 0; q < 4; q++) acc[i][j][q] = 0.f;

    const int K_ITERS = IN_DIM / BK;
    load_stage(0, 0);
    for (int it = 0; it < K_ITERS; it++) {
        if (it + 1 < K_ITERS) {
            load_stage((it + 1) & 1, (it + 1) * BK);
            CP_WAIT(1);
        } else {
            CP_WAIT(0);
        }
        __syncthreads();

        __nv_bfloat16* As_hi = smem + (it & 1) * STAGE_ELEMS;
        __nv_bfloat16* As_lo = As_hi + 5120;
        __nv_bfloat16* Bs_hi = As_hi + 10240;
        __nv_bfloat16* Bs_lo = As_hi + 12800;

        #pragma unroll
        for (int ks = 0; ks < 2; ks++) {
            const int kc = ks * 16 + 2 * (lane & 3);
            uint32_t ah[4][4], al[4][4];
            #pragma unroll
            for (int i = 0; i < 4; i++) {
                int r = warp_m * 64 + i * 16 + (lane >> 2);
                ah[i][0] = *reinterpret_cast<uint32_t*>(&As_hi[r * KPAD + kc]);
                ah[i][1] = *reinterpret_cast<uint32_t*>(&As_hi[(r + 8) * KPAD + kc]);
                ah[i][2] = *reinterpret_cast<uint32_t*>(&As_hi[r * KPAD + kc + 8]);
                ah[i][3] = *reinterpret_cast<uint32_t*>(&As_hi[(r + 8) * KPAD + kc + 8]);
                al[i][0] = *reinterpret_cast<uint32_t*>(&As_lo[r * KPAD + kc]);
                al[i][1] = *reinterpret_cast<uint32_t*>(&As_lo[(r + 8) * KPAD + kc]);
                al[i][2] = *reinterpret_cast<uint32_t*>(&As_lo[r * KPAD + kc + 8]);
                al[i][3] = *reinterpret_cast<uint32_t*>(&As_lo[(r + 8) * KPAD + kc + 8]);
            }
            #pragma unroll
            for (int j = 0; j < 2; j++) {
                int c = warp_n * 16 + j * 8 + (lane >> 2);
                uint32_t bh0 = *reinterpret_cast<uint32_t*>(&Bs_hi[c * KPAD + kc]);
                uint32_t bh1 = *reinterpret_cast<uint32_t*>(&Bs_hi[c * KPAD + kc + 8]);
                uint32_t bl0 = *reinterpret_cast<uint32_t*>(&Bs_lo[c * KPAD + kc]);
                uint32_t bl1 = *reinterpret_cast<uint32_t*>(&Bs_lo[c * KPAD + kc + 8]);
                #pragma unroll
                for (int i = 0; i < 4; i++) {
                    MMA_BF16(acc[i][j], ah[i], bh0, bh1);
                    MMA_BF16(acc[i][j], ah[i], bl0, bl1);
                    MMA_BF16(acc[i][j], al[i], bh0, bh1);
                }
            }
        }
        __syncthreads();
    }

    #pragma unroll
    for (int i = 0; i < 4; i++) {
        int r = warp_m * 64 + i * 16 + (lane >> 2);
        #pragma unroll
        for (int j = 0; j < 2; j++) {
            int c0 = n0 + warp_n * 16 + j * 8 + 2 * (lane & 3);
            float bb0 = b1[c0], bb1 = b1[c0 + 1];
            float p0 = fminf(fmaxf(p[c0], 0.f), 1.f);
            float p1 = fminf(fmaxf(p[c0 + 1], 0.f), 1.f);
            #pragma unroll
            for (int hrow = 0; hrow < 2; hrow++) {
                int grow = m0 + r + 8 * hrow;
                if (grow >= n_nodes) continue;
                float v0 = fmaxf(acc[i][j][2 * hrow + 0] + bb0, 0.f) * p0;
                float v1 = fmaxf(acc[i][j][2 * hrow + 1] + bb1, 0.f) * p1;
                __nv_bfloat16 h0, l0, h1, l1;
                split_bf16(v0, h0, l0);
                split_bf16(v1, h1, l1);
                *reinterpret_cast<__nv_bfloat162*>(&g_hid_hi[(size_t)grow * HID_DIM + c0]) = __nv_bfloat162(h0, h1);
                *reinterpret_cast<__nv_bfloat162*>(&g_hid_lo[(size_t)grow * HID_DIM + c0]) = __nv_bfloat162(l0, l1);
            }
        }
    }
}

// GEMM2: ypre16 = fp16((hidden @ W2) * norm_src[row]); cp.async double-buffered
__global__ __launch_bounds__(256) void k_gemm2(int n_nodes) {
    extern __shared__ __nv_bfloat16 smem[];
    const int m0 = blockIdx.x * BM;
    const int tid = threadIdx.x;
    const int lane = tid & 31;
    const int wid = tid >> 5;
    const int warp_m = wid >> 2;
    const int warp_n = wid & 3;
    const int bn = tid >> 2;
    const int bq = tid & 3;

    auto load_stage = [&](int s, int k0) {
        __nv_bfloat16* As_hi = smem + s * STAGE_ELEMS;
        __nv_bfloat16* As_lo = As_hi + 5120;
        __nv_bfloat16* Bs_hi = As_hi + 10240;
        __nv_bfloat16* Bs_lo = As_hi + 12800;
        #pragma unroll
        for (int i = 0; i < 2; i++) {
            int idx = tid + 256 * i;
            int row = idx >> 2;
            int q = idx & 3;
            cp16(&As_hi[row * KPAD + 8 * q], &g_hid_hi[(size_t)(m0 + row) * HID_DIM + k0 + 8 * q]);
            cp16(&As_lo[row * KPAD + 8 * q], &g_hid_lo[(size_t)(m0 + row) * HID_DIM + k0 + 8 * q]);
        }
        cp16(&Bs_hi[bn * KPAD + 8 * bq], &g_w2t_hi[(size_t)bn * HID_DIM + k0 + 8 * bq]);
        cp16(&Bs_lo[bn * KPAD + 8 * bq], &g_w2t_lo[(size_t)bn * HID_DIM + k0 + 8 * bq]);
        CP_COMMIT();
    };

    float acc[4][2][4];
    #pragma unroll
    for (int i = 0; i < 4; i++)
        #pragma unroll
        for (int j = 0; j < 2; j++)
            #pragma unroll
            for (int q = 0; q < 4; q++) acc[i][j][q] = 0.f;

    const int K_ITERS = HID_DIM / BK;
    load_stage(0, 0);
    for (int it = 0; it < K_ITERS; it++) {
        if (it + 1 < K_ITERS) {
            load_stage((it + 1) & 1, (it + 1) * BK);
            CP_WAIT(1);
        } else {
            CP_WAIT(0);
        }
        __syncthreads();

        __nv_bfloat16* As_hi = smem + (it & 1) * STAGE_ELEMS;
        __nv_bfloat16* As_lo = As_hi + 5120;
        __nv_bfloat16* Bs_hi = As_hi + 10240;
        __nv_bfloat16* Bs_lo = As_hi + 12800;

        #pragma unroll
        for (int ks = 0; ks < 2; ks++) {
            const int kc = ks * 16 + 2 * (lane & 3);
            uint32_t ah[4][4], al[4][4];
            #pragma unroll
            for (int i = 0; i < 4; i++) {
                int r = warp_m * 64 + i * 16 + (lane >> 2);
                ah[i][0] = *reinterpret_cast<uint32_t*>(&As_hi[r * KPAD + kc]);
                ah[i][1] = *reinterpret_cast<uint32_t*>(&As_hi[(r + 8) * KPAD + kc]);
                ah[i][2] = *reinterpret_cast<uint32_t*>(&As_hi[r * KPAD + kc + 8]);
                ah[i][3] = *reinterpret_cast<uint32_t*>(&As_hi[(r + 8) * KPAD + kc + 8]);
                al[i][0] = *reinterpret_cast<uint32_t*>(&As_lo[r * KPAD + kc]);
                al[i][1] = *reinterpret_cast<uint32_t*>(&As_lo[(r + 8) * KPAD + kc]);
                al[i][2] = *reinterpret_cast<uint32_t*>(&As_lo[r * KPAD + kc + 8]);
                al[i][3] = *reinterpret_cast<uint32_t*>(&As_lo[(r + 8) * KPAD + kc + 8]);
            }
            #pragma unroll
            for (int j = 0; j < 2; j++) {
                int c = warp_n * 16 + j * 8 + (lane >> 2);
                uint32_t bh0 = *reinterpret_cast<uint32_t*>(&Bs_hi[c * KPAD + kc]);
                uint32_t bh1 = *reinterpret_cast<uint32_t*>(&Bs_hi[c * KPAD + kc + 8]);
                uint32_t bl0 = *reinterpret_cast<uint32_t*>(&Bs_lo[c * KPAD + kc]);
                uint32_t bl1 = *reinterpret_cast<uint32_t*>(&Bs_lo[c * KPAD + kc + 8]);
                #pragma unroll
                for (int i = 0; i < 4; i++) {
                    MMA_BF16(acc[i][j], ah[i], bh0, bh1);
                    MMA_BF16(acc[i][j], ah[i], bl0, bl1);
                    MMA_BF16(acc[i][j], al[i], bh0, bh1);
                }
            }
        }
        __syncthreads();
    }

    #pragma unroll
    for (int i = 0; i < 4; i++) {
        int r = warp_m * 64 + i * 16 + (lane >> 2);
        #pragma unroll
        for (int j = 0; j < 2; j++) {
            int c0 = warp_n * 16 + j * 8 + 2 * (lane & 3);
            #pragma unroll
            for (int hrow = 0; hrow < 2; hrow++) {
                int grow = m0 + r + 8 * hrow;
                if (grow >= n_nodes) continue;
                float ns = g_norm_src[grow];
                __half2 v = __floats2half2_rn(acc[i][j][2 * hrow + 0] * ns,
                                              acc[i][j][2 * hrow + 1] * ns);
                *reinterpret_cast<__half2*>(&g_ypre16[(size_t)grow * OUT_DIM + c0]) = v;
            }
        }
    }
}

// ---------------- SpMM2: out16[dst] += fp16(ypre16[src]*norm_dst[dst]) (fp16x2 REDs) ----------------
// half-warp per edge (16 lanes x uint2 = 128B row), 8 edges/warp
__global__ void k_spmm2(const int* __restrict__ src, const int* __restrict__ dst,
                        int n_edges) {
    int w = (blockIdx.x * blockDim.x + threadIdx.x) >> 5;
    int lane = threadIdx.x & 31;
    int half_id = lane >> 4;
    int l = lane & 15;
    int e0 = w * 8;
    if (e0 >= n_edges) return;
    int s[4], d[4];
    #pragma unroll
    for (int i = 0; i < 4; i++) {
        int e = min(e0 + 2 * i + half_id, n_edges - 1);
        s[i] = __ldg(&src[e]);
        d[i] = __ldg(&dst[e]);
    }
    float nd[4];
    #pragma unroll
    for (int i = 0; i < 4; i++) nd[i] = g_norm_dst[d[i]];
    uint2 v[4];
    #pragma unroll
    for (int i = 0; i < 4; i++)
        v[i] = reinterpret_cast<const uint2*>(g_ypre16 + (size_t)s[i] * OUT_DIM)[l];
    #pragma unroll
    for (int i = 0; i < 4; i++) {
        if (e0 + 2 * i + half_id >= n_edges) break;
        __half2 a = *reinterpret_cast<__half2*>(&v[i].x);
        __half2 b = *reinterpret_cast<__half2*>(&v[i].y);
        float2 fa = __half22float2(a);
        float2 fb = __half22float2(b);
        __half2 ta = __floats2half2_rn(fa.x * nd[i], fa.y * nd[i]);
        __half2 tb = __floats2half2_rn(fb.x * nd[i], fb.y * nd[i]);
        uint32_t pa = *reinterpret_cast<uint32_t*>(&ta);
        uint32_t pb = *reinterpret_cast<uint32_t*>(&tb);
        uint2* orow = reinterpret_cast<uint2*>(g_out16 + (size_t)d[i] * OUT_DIM);
        asm volatile("red.global.add.noftz.v2.f16x2 [%0], {%1,%2};"
                     :: "l"(orow + l), "r"(pa), "r"(pb)
                     : "memory");
    }
}

// ---------------- final: out = fp32(out16) + b2[col] ----------------
__global__ void k_final(float* __restrict__ out, const float* __restrict__ b2, int n_nodes) {
    int i = blockIdx.x * blockDim.x + threadIdx.x;
    const int total = n_nodes * (OUT_DIM / 4);   // float4 units
    if (i >= total) return;
    int c4 = i & 15;                             // 16 float4 per row
    uint2 v = reinterpret_cast<const uint2*>(g_out16)[i];
    float2 f0 = __half22float2(*reinterpret_cast<__half2*>(&v.x));
    float2 f1 = __half22float2(*reinterpret_cast<__half2*>(&v.y));
    const float4 bb = __ldg(&reinterpret_cast<const float4*>(b2)[c4]);
    float4 o;
    o.x = f0.x + bb.x;
    o.y = f0.y + bb.y;
    o.z = f1.x + bb.z;
    o.w = f1.y + bb.w;
    reinterpret_cast<float4*>(out)[i] = o;
}

// ---------------- launch ----------------
extern "C" void kernel_launch(void* const* d_in, const int* in_sizes, int n_in,
                              void* d_out, int out_size) {
    const float* h  = (const float*)d_in[0];
    const float* W1 = (const float*)d_in[1];
    const float* b1 = (const float*)d_in[2];
    const float* W2 = (const float*)d_in[3];
    const float* b2 = (const float*)d_in[4];
    const float* p  = (const float*)d_in[5];
    const int* src  = (const int*)d_in[6];
    const int* dst  = (const int*)d_in[7];

    const int n_nodes = in_sizes[0] / IN_DIM;   // 100000
    const int n_edges = in_sizes[6];            // 1600000
    float* out = (float*)d_out;

    cudaFuncSetAttribute(k_gemm1, cudaFuncAttributeMaxDynamicSharedMemorySize, SMEM_BYTES);
    cudaFuncSetAttribute(k_gemm2, cudaFuncAttributeMaxDynamicSharedMemorySize, SMEM_BYTES);

    k_zero<<<2048, 256>>>();
    k_degree<<<(n_edges + 255) / 256, 256>>>(src, dst, n_edges);
    k_norm<<<(n_nodes + 255) / 256, 256>>>(n_nodes);
    k_prep<<<2048, 256>>>(h, W1, W2);

    // SpMM1: fp16x2 REDs, 8 edges/warp
    {
        int warps = (n_edges + 7) / 8;
        k_spmm1<<<(warps + 7) / 8, 256>>>(src, dst, n_edges);
    }
    k_split<<<2048, 256>>>();
    // GEMM1
    {
        dim3 grid(NN_PAD / BM, HID_DIM / BN);   // 782 x 4
        k_gemm1<<<grid, 256, SMEM_BYTES>>>(b1, p, n_nodes);
    }
    // GEMM2
    {
        dim3 grid(NN_PAD / BM, 1);              // 782
        k_gemm2<<<grid, 256, SMEM_BYTES>>>(n_nodes);
    }
    // SpMM2: fp16x2 REDs, fused norm_dst
    {
        int warps = (n_edges + 7) / 8;
        k_spmm2<<<(warps + 7) / 8, 256>>>(src, dst, n_edges);
    }
    // final convert + bias
    k_final<<<(n_nodes * (OUT_DIM / 4) + 255) / 256, 256>>>(out, b2, n_nodes);
}

// round 15
// speedup vs baseline: 1.5063x; 1.0827x over previous
#include <cuda_runtime.h>
#include <cuda_bf16.h>
#include <cuda_fp16.h>
#include <stdint.h>

#define NN 100000
#define NN_PAD 100096
#define NE 1600000
#define IN_DIM 128
#define HID_DIM 256
#define OUT_DIM 64

// ---------------- device scratch ----------------
__device__ __align__(16) float g_norm_src[NN_PAD];
__device__ __align__(16) float g_norm_dst[NN_PAD];
__device__ __align__(16) __half g_h16[(size_t)NN * IN_DIM];            // fp16(h * norm_src[row])
__device__ __align__(16) __half g_xagg16[(size_t)NN_PAD * IN_DIM];     // fp16 accumulator (RED target)
__device__ __align__(16) __half g_out16[(size_t)NN * OUT_DIM];         // fp16 output accumulator
__device__ __align__(16) __half g_w1t_hi[HID_DIM * IN_DIM];            // fp16 split, [n][k]
__device__ __align__(16) __half g_w1t_lo[HID_DIM * IN_DIM];
__device__ __align__(16) __nv_bfloat16 g_w2t_hi[OUT_DIM * HID_DIM];    // bf16 split, [n][k]
__device__ __align__(16) __nv_bfloat16 g_w2t_lo[OUT_DIM * HID_DIM];
__device__ __align__(16) __nv_bfloat16 g_hid_hi[(size_t)NN_PAD * HID_DIM];
__device__ __align__(16) __nv_bfloat16 g_hid_lo[(size_t)NN_PAD * HID_DIM];
__device__ __align__(16) __half g_ypre16[(size_t)NN * OUT_DIM];

__device__ __forceinline__ void split_bf16(float v, __nv_bfloat16& hi, __nv_bfloat16& lo) {
    hi = __float2bfloat16(v);
    lo = __float2bfloat16(v - __bfloat162float(hi));
}
__device__ __forceinline__ void split_fp16(float v, __half& hi, __half& lo) {
    hi = __float2half_rn(v);
    lo = __float2half_rn(v - __half2float(hi));
}

#define MMA_BF16(d, a, b0, b1)                                                  \
    asm volatile("mma.sync.aligned.m16n8k16.row.col.f32.bf16.bf16.f32 "         \
                 "{%0,%1,%2,%3}, {%4,%5,%6,%7}, {%8,%9}, {%0,%1,%2,%3};"        \
                 : "+f"(d[0]), "+f"(d[1]), "+f"(d[2]), "+f"(d[3])               \
                 : "r"(a[0]), "r"(a[1]), "r"(a[2]), "r"(a[3]), "r"(b0), "r"(b1))

#define MMA_F16(d, a, b0, b1)                                                   \
    asm volatile("mma.sync.aligned.m16n8k16.row.col.f32.f16.f16.f32 "           \
                 "{%0,%1,%2,%3}, {%4,%5,%6,%7}, {%8,%9}, {%0,%1,%2,%3};"        \
                 : "+f"(d[0]), "+f"(d[1]), "+f"(d[2]), "+f"(d[3])               \
                 : "r"(a[0]), "r"(a[1]), "r"(a[2]), "r"(a[3]), "r"(b0), "r"(b1))

__device__ __forceinline__ void cp16(void* smem_dst, const void* gmem_src) {
    uint32_t s = (uint32_t)__cvta_generic_to_shared(smem_dst);
    asm volatile("cp.async.cg.shared.global [%0], [%1], 16;" :: "r"(s), "l"(gmem_src) : "memory");
}
#define CP_COMMIT() asm volatile("cp.async.commit_group;" ::: "memory")
#define CP_WAIT(n)  asm volatile("cp.async.wait_group %0;" :: "n"(n) : "memory")

// ---------------- zero init ----------------
__global__ void k_zero() {
    int i = blockIdx.x * blockDim.x + threadIdx.x;
    int stride = gridDim.x * blockDim.x;
    const uint4 z4 = make_uint4(0u, 0u, 0u, 0u);
    // zero fp16 xagg accumulator (incl. pad rows -> gemm1 A pads are zero)
    const int nxa = NN_PAD * (IN_DIM / 8);
    uint4* xa = reinterpret_cast<uint4*>(g_xagg16);
    for (int j = i; j < nxa; j += stride) xa[j] = z4;
    // zero fp16 out accumulator
    const int nout = NN * (OUT_DIM / 8);
    uint4* o16 = reinterpret_cast<uint4*>(g_out16);
    for (int j = i; j < nout; j += stride) o16[j] = z4;
    for (int j = i; j < NN_PAD; j += stride) { g_norm_src[j] = 0.f; g_norm_dst[j] = 0.f; }
    // hid pad rows (read by gemm2 A tiles) must be zero
    const int hid_pad = (NN_PAD - NN) * (HID_DIM / 8);
    uint4* hh = reinterpret_cast<uint4*>(g_hid_hi + (size_t)NN * HID_DIM);
    uint4* hl = reinterpret_cast<uint4*>(g_hid_lo + (size_t)NN * HID_DIM);
    for (int j = i; j < hid_pad; j += stride) { hh[j] = z4; hl[j] = z4; }
}

// ---------------- degrees ----------------
__global__ void k_degree(const int* __restrict__ src, const int* __restrict__ dst, int n_edges) {
    int i = blockIdx.x * blockDim.x + threadIdx.x;
    int stride = gridDim.x * blockDim.x;
    for (int e = i; e < n_edges; e += stride) {
        atomicAdd(&g_norm_src[src[e]], 1.0f);
        atomicAdd(&g_norm_dst[dst[e]], 1.0f);
    }
}

__global__ void k_norm(int n_nodes) {
    int i = blockIdx.x * blockDim.x + threadIdx.x;
    if (i < n_nodes) {
        g_norm_src[i] = rsqrtf(fmaxf(g_norm_src[i], 1.0f));
        g_norm_dst[i] = rsqrtf(fmaxf(g_norm_dst[i], 1.0f));
    }
}

// ---------------- prep: h16 = fp16(h * norm_src[row]); W1 fp16-split; W2 bf16-split ----------------
__global__ void k_prep(const float* __restrict__ h,
                       const float* __restrict__ W1, const float* __restrict__ W2) {
    int i = blockIdx.x * blockDim.x + threadIdx.x;
    int stride = gridDim.x * blockDim.x;
    const int n1 = HID_DIM * IN_DIM;
    const int n2 = OUT_DIM * HID_DIM;
    for (int j = i; j < n1 + n2; j += stride) {
        if (j < n1) {
            int n = j / IN_DIM, k = j % IN_DIM;
            float v = W1[(size_t)k * HID_DIM + n];
            __half hi, lo;
            split_fp16(v, hi, lo);
            g_w1t_hi[j] = hi; g_w1t_lo[j] = lo;
        } else {
            int jj = j - n1;
            int n = jj / HID_DIM, k = jj % HID_DIM;
            float v = W2[(size_t)k * OUT_DIM + n];
            __nv_bfloat16 hi, lo;
            split_bf16(v, hi, lo);
            g_w2t_hi[jj] = hi; g_w2t_lo[jj] = lo;
        }
    }
    const int nh4 = NN * (IN_DIM / 4);
    for (int j = i; j < nh4; j += stride) {
        int row = j >> 5;
        float ns = g_norm_src[row];
        float4 v = reinterpret_cast<const float4*>(h)[j];
        __half2 a = __floats2half2_rn(v.x * ns, v.y * ns);
        __half2 b = __floats2half2_rn(v.z * ns, v.w * ns);
        uint2 pk;
        pk.x = *reinterpret_cast<uint32_t*>(&a);
        pk.y = *reinterpret_cast<uint32_t*>(&b);
        reinterpret_cast<uint2*>(g_h16)[j] = pk;
    }
}

// ---------------- SpMM1: xagg16[dst] += h16[src]  (fp16x2 REDs) ----------------
__global__ void k_spmm1(const int* __restrict__ src, const int* __restrict__ dst,
                        int n_edges) {
    int w = (blockIdx.x * blockDim.x + threadIdx.x) >> 5;
    int lane = threadIdx.x & 31;
    int half_id = lane >> 4;
    int l = lane & 15;
    int e0 = w * 8;
    if (e0 >= n_edges) return;
    int s[4], d[4];
    #pragma unroll
    for (int i = 0; i < 4; i++) {
        int e = min(e0 + 2 * i + half_id, n_edges - 1);
        s[i] = __ldg(&src[e]);
        d[i] = __ldg(&dst[e]);
    }
    uint4 v[4];
    #pragma unroll
    for (int i = 0; i < 4; i++)
        v[i] = reinterpret_cast<const uint4*>(g_h16 + (size_t)s[i] * IN_DIM)[l];
    #pragma unroll
    for (int i = 0; i < 4; i++) {
        if (e0 + 2 * i + half_id >= n_edges) break;
        uint4* orow = reinterpret_cast<uint4*>(g_xagg16 + (size_t)d[i] * IN_DIM);
        asm volatile("red.global.add.noftz.v4.f16x2 [%0], {%1,%2,%3,%4};"
                     :: "l"(orow + l), "r"(v[i].x), "r"(v[i].y), "r"(v[i].z), "r"(v[i].w)
                     : "memory");
    }
}

// ---------------- GEMM tiles ----------------
#define BM 128
#define BN 64
#define BK 32
#define KPAD 40
// gemm1 stage (halves): As[BM*KPAD]=5120 @0, Bs_hi[BN*KPAD]=2560 @5120, Bs_lo @7680
#define G1_STAGE 10240
#define G1_SMEM_BYTES (2 * G1_STAGE * 2)
// gemm2 stage (bf16): As_hi 5120 @0, As_lo @5120, Bs_hi @10240, Bs_lo @12800
#define G2_STAGE 15360
#define G2_SMEM_BYTES (2 * G2_STAGE * 2)

// GEMM1: hidden = relu(norm_dst*(xagg16 @ W1) + b1) * clip(p,0,1)
// A = fp16 xagg16 (exact), B = fp16-split W1; 2 MMA terms
__global__ __launch_bounds__(256) void k_gemm1(const float* __restrict__ b1,
                                               const float* __restrict__ p,
                                               int n_nodes) {
    extern __shared__ __half smem_h[];
    const int m0 = blockIdx.x * BM;
    const int n0 = blockIdx.y * BN;
    const int tid = threadIdx.x;
    const int lane = tid & 31;
    const int wid = tid >> 5;
    const int warp_m = wid >> 2;
    const int warp_n = wid & 3;
    const int bn = tid >> 2;
    const int bq = tid & 3;

    auto load_stage = [&](int s, int k0) {
        __half* As = smem_h + s * G1_STAGE;
        __half* Bs_hi = As + 5120;
        __half* Bs_lo = As + 7680;
        // A: 512 16B chunks, 2/thread
        #pragma unroll
        for (int i = 0; i < 2; i++) {
            int idx = tid + 256 * i;
            int row = idx >> 2;
            int q = idx & 3;
            cp16(&As[row * KPAD + 8 * q], &g_xagg16[(size_t)(m0 + row) * IN_DIM + k0 + 8 * q]);
        }
        // B: 256 chunks per array, 1/thread
        cp16(&Bs_hi[bn * KPAD + 8 * bq], &g_w1t_hi[(size_t)(n0 + bn) * IN_DIM + k0 + 8 * bq]);
        cp16(&Bs_lo[bn * KPAD + 8 * bq], &g_w1t_lo[(size_t)(n0 + bn) * IN_DIM + k0 + 8 * bq]);
        CP_COMMIT();
    };

    float acc[4][2][4];
    #pragma unroll
    for (int i = 0; i < 4; i++)
        #pragma unroll
        for (int j = 0; j < 2; j++)
            #pragma unroll
            for (int q = 0; q < 4; q++) acc[i][j][q] = 0.f;

    const int K_ITERS = IN_DIM / BK;
    load_stage(0, 0);
    for (int it = 0; it < K_ITERS; it++) {
        if (it + 1 < K_ITERS) {
            load_stage((it + 1) & 1, (it + 1) * BK);
            CP_WAIT(1);
        } else {
            CP_WAIT(0);
        }
        __syncthreads();

        __half* As = smem_h + (it & 1) * G1_STAGE;
        __half* Bs_hi = As + 5120;
        __half* Bs_lo = As + 7680;

        #pragma unroll
        for (int ks = 0; ks < 2; ks++) {
            const int kc = ks * 16 + 2 * (lane & 3);
            uint32_t a[4][4];
            #pragma unroll
            for (int i = 0; i < 4; i++) {
                int r = warp_m * 64 + i * 16 + (lane >> 2);
                a[i][0] = *reinterpret_cast<uint32_t*>(&As[r * KPAD + kc]);
                a[i][1] = *reinterpret_cast<uint32_t*>(&As[(r + 8) * KPAD + kc]);
                a[i][2] = *reinterpret_cast<uint32_t*>(&As[r * KPAD + kc + 8]);
                a[i][3] = *reinterpret_cast<uint32_t*>(&As[(r + 8) * KPAD + kc + 8]);
            }
            #pragma unroll
            for (int j = 0; j < 2; j++) {
                int c = warp_n * 16 + j * 8 + (lane >> 2);
                uint32_t bh0 = *reinterpret_cast<uint32_t*>(&Bs_hi[c * KPAD + kc]);
                uint32_t bh1 = *reinterpret_cast<uint32_t*>(&Bs_hi[c * KPAD + kc + 8]);
                uint32_t bl0 = *reinterpret_cast<uint32_t*>(&Bs_lo[c * KPAD + kc]);
                uint32_t bl1 = *reinterpret_cast<uint32_t*>(&Bs_lo[c * KPAD + kc + 8]);
                #pragma unroll
                for (int i = 0; i < 4; i++) {
                    MMA_F16(acc[i][j], a[i], bh0, bh1);
                    MMA_F16(acc[i][j], a[i], bl0, bl1);
                }
            }
        }
        __syncthreads();
    }

    // epilogue: * norm_dst[row], + bias, relu, * p, split-bf16 store
    #pragma unroll
    for (int i = 0; i < 4; i++) {
        int r = warp_m * 64 + i * 16 + (lane >> 2);
        #pragma unroll
        for (int j = 0; j < 2; j++) {
            int c0 = n0 + warp_n * 16 + j * 8 + 2 * (lane & 3);
            float bb0 = b1[c0], bb1 = b1[c0 + 1];
            float p0 = fminf(fmaxf(p[c0], 0.f), 1.f);
            float p1 = fminf(fmaxf(p[c0 + 1], 0.f), 1.f);
            #pragma unroll
            for (int hrow = 0; hrow < 2; hrow++) {
                int grow = m0 + r + 8 * hrow;
                if (grow >= n_nodes) continue;
                float nd = g_norm_dst[grow];
                float v0 = fmaxf(acc[i][j][2 * hrow + 0] * nd + bb0, 0.f) * p0;
                float v1 = fmaxf(acc[i][j][2 * hrow + 1] * nd + bb1, 0.f) * p1;
                __nv_bfloat16 h0, l0, h1, l1;
                split_bf16(v0, h0, l0);
                split_bf16(v1, h1, l1);
                *reinterpret_cast<__nv_bfloat162*>(&g_hid_hi[(size_t)grow * HID_DIM + c0]) = __nv_bfloat162(h0, h1);
                *reinterpret_cast<__nv_bfloat162*>(&g_hid_lo[(size_t)grow * HID_DIM + c0]) = __nv_bfloat162(l0, l1);
            }
        }
    }
}

// GEMM2: ypre16 = fp16((hidden @ W2) * norm_src[row]); bf16-split path (unchanged)
__global__ __launch_bounds__(256) void k_gemm2(int n_nodes) {
    extern __shared__ __nv_bfloat16 smem[];
    const int m0 = blockIdx.x * BM;
    const int tid = threadIdx.x;
    const int lane = tid & 31;
    const int wid = tid >> 5;
    const int warp_m = wid >> 2;
    const int warp_n = wid & 3;
    const int bn = tid >> 2;
    const int bq = tid & 3;

    auto load_stage = [&](int s, int k0) {
        __nv_bfloat16* As_hi = smem + s * G2_STAGE;
        __nv_bfloat16* As_lo = As_hi + 5120;
        __nv_bfloat16* Bs_hi = As_hi + 10240;
        __nv_bfloat16* Bs_lo = As_hi + 12800;
        #pragma unroll
        for (int i = 0; i < 2; i++) {
            int idx = tid + 256 * i;
            int row = idx >> 2;
            int q = idx & 3;
            cp16(&As_hi[row * KPAD + 8 * q], &g_hid_hi[(size_t)(m0 + row) * HID_DIM + k0 + 8 * q]);
            cp16(&As_lo[row * KPAD + 8 * q], &g_hid_lo[(size_t)(m0 + row) * HID_DIM + k0 + 8 * q]);
        }
        cp16(&Bs_hi[bn * KPAD + 8 * bq], &g_w2t_hi[(size_t)bn * HID_DIM + k0 + 8 * bq]);
        cp16(&Bs_lo[bn * KPAD + 8 * bq], &g_w2t_lo[(size_t)bn * HID_DIM + k0 + 8 * bq]);
        CP_COMMIT();
    };

    float acc[4][2][4];
    #pragma unroll
    for (int i = 0; i < 4; i++)
        #pragma unroll
        for (int j = 0; j < 2; j++)
            #pragma unroll
            for (int q = 0; q < 4; q++) acc[i][j][q] = 0.f;

    const int K_ITERS = HID_DIM / BK;
    load_stage(0, 0);
    for (int it = 0; it < K_ITERS; it++) {
        if (it + 1 < K_ITERS) {
            load_stage((it + 1) & 1, (it + 1) * BK);
            CP_WAIT(1);
        } else {
            CP_WAIT(0);
        }
        __syncthreads();

        __nv_bfloat16* As_hi = smem + (it & 1) * G2_STAGE;
        __nv_bfloat16* As_lo = As_hi + 5120;
        __nv_bfloat16* Bs_hi = As_hi + 10240;
        __nv_bfloat16* Bs_lo = As_hi + 12800;

        #pragma unroll
        for (int ks = 0; ks < 2; ks++) {
            const int kc = ks * 16 + 2 * (lane & 3);
            uint32_t ah[4][4], al[4][4];
            #pragma unroll
            for (int i = 0; i < 4; i++) {
                int r = warp_m * 64 + i * 16 + (lane >> 2);
                ah[i][0] = *reinterpret_cast<uint32_t*>(&As_hi[r * KPAD + kc]);
                ah[i][1] = *reinterpret_cast<uint32_t*>(&As_hi[(r + 8) * KPAD + kc]);
                ah[i][2] = *reinterpret_cast<uint32_t*>(&As_hi[r * KPAD + kc + 8]);
                ah[i][3] = *reinterpret_cast<uint32_t*>(&As_hi[(r + 8) * KPAD + kc + 8]);
                al[i][0] = *reinterpret_cast<uint32_t*>(&As_lo[r * KPAD + kc]);
                al[i][1] = *reinterpret_cast<uint32_t*>(&As_lo[(r + 8) * KPAD + kc]);
                al[i][2] = *reinterpret_cast<uint32_t*>(&As_lo[r * KPAD + kc + 8]);
                al[i][3] = *reinterpret_cast<uint32_t*>(&As_lo[(r + 8) * KPAD + kc + 8]);
            }
            #pragma unroll
            for (int j = 0; j < 2; j++) {
                int c = warp_n * 16 + j * 8 + (lane >> 2);
                uint32_t bh0 = *reinterpret_cast<uint32_t*>(&Bs_hi[c * KPAD + kc]);
                uint32_t bh1 = *reinterpret_cast<uint32_t*>(&Bs_hi[c * KPAD + kc + 8]);
                uint32_t bl0 = *reinterpret_cast<uint32_t*>(&Bs_lo[c * KPAD + kc]);
                uint32_t bl1 = *reinterpret_cast<uint32_t*>(&Bs_lo[c * KPAD + kc + 8]);
                #pragma unroll
                for (int i = 0; i < 4; i++) {
                    MMA_BF16(acc[i][j], ah[i], bh0, bh1);
                    MMA_BF16(acc[i][j], ah[i], bl0, bl1);
                    MMA_BF16(acc[i][j], al[i], bh0, bh1);
                }
            }
        }
        __syncthreads();
    }

    #pragma unroll
    for (int i = 0; i < 4; i++) {
        int r = warp_m * 64 + i * 16 + (lane >> 2);
        #pragma unroll
        for (int j = 0; j < 2; j++) {
            int c0 = warp_n * 16 + j * 8 + 2 * (lane & 3);
            #pragma unroll
            for (int hrow = 0; hrow < 2; hrow++) {
                int grow = m0 + r + 8 * hrow;
                if (grow >= n_nodes) continue;
                float ns = g_norm_src[grow];
                __half2 v = __floats2half2_rn(acc[i][j][2 * hrow + 0] * ns,
                                              acc[i][j][2 * hrow + 1] * ns);
                *reinterpret_cast<__half2*>(&g_ypre16[(size_t)grow * OUT_DIM + c0]) = v;
            }
        }
    }
}

// ---------------- SpMM2: out16[dst] += fp16(ypre16[src]*norm_dst[dst]) (fp16x2 REDs) ----------------
__global__ void k_spmm2(const int* __restrict__ src, const int* __restrict__ dst,
                        int n_edges) {
    int w = (blockIdx.x * blockDim.x + threadIdx.x) >> 5;
    int lane = threadIdx.x & 31;
    int half_id = lane >> 4;
    int l = lane & 15;
    int e0 = w * 8;
    if (e0 >= n_edges) return;
    int s[4], d[4];
    #pragma unroll
    for (int i = 0; i < 4; i++) {
        int e = min(e0 + 2 * i + half_id, n_edges - 1);
        s[i] = __ldg(&src[e]);
        d[i] = __ldg(&dst[e]);
    }
    float nd[4];
    #pragma unroll
    for (int i = 0; i < 4; i++) nd[i] = g_norm_dst[d[i]];
    uint2 v[4];
    #pragma unroll
    for (int i = 0; i < 4; i++)
        v[i] = reinterpret_cast<const uint2*>(g_ypre16 + (size_t)s[i] * OUT_DIM)[l];
    #pragma unroll
    for (int i = 0; i < 4; i++) {
        if (e0 + 2 * i + half_id >= n_edges) break;
        __half2 a = *reinterpret_cast<__half2*>(&v[i].x);
        __half2 b = *reinterpret_cast<__half2*>(&v[i].y);
        float2 fa = __half22float2(a);
        float2 fb = __half22float2(b);
        __half2 ta = __floats2half2_rn(fa.x * nd[i], fa.y * nd[i]);
        __half2 tb = __floats2half2_rn(fb.x * nd[i], fb.y * nd[i]);
        uint32_t pa = *reinterpret_cast<uint32_t*>(&ta);
        uint32_t pb = *reinterpret_cast<uint32_t*>(&tb);
        uint2* orow = reinterpret_cast<uint2*>(g_out16 + (size_t)d[i] * OUT_DIM);
        asm volatile("red.global.add.noftz.v2.f16x2 [%0], {%1,%2};"
                     :: "l"(orow + l), "r"(pa), "r"(pb)
                     : "memory");
    }
}

// ---------------- final: out = fp32(out16) + b2[col] ----------------
__global__ void k_final(float* __restrict__ out, const float* __restrict__ b2, int n_nodes) {
    int i = blockIdx.x * blockDim.x + threadIdx.x;
    const int total = n_nodes * (OUT_DIM / 4);
    if (i >= total) return;
    int c4 = i & 15;
    uint2 v = reinterpret_cast<const uint2*>(g_out16)[i];
    float2 f0 = __half22float2(*reinterpret_cast<__half2*>(&v.x));
    float2 f1 = __half22float2(*reinterpret_cast<__half2*>(&v.y));
    const float4 bb = __ldg(&reinterpret_cast<const float4*>(b2)[c4]);
    float4 o;
    o.x = f0.x + bb.x;
    o.y = f0.y + bb.y;
    o.z = f1.x + bb.z;
    o.w = f1.y + bb.w;
    reinterpret_cast<float4*>(out)[i] = o;
}

// ---------------- launch ----------------
extern "C" void kernel_launch(void* const* d_in, const int* in_sizes, int n_in,
                              void* d_out, int out_size) {
    const float* h  = (const float*)d_in[0];
    const float* W1 = (const float*)d_in[1];
    const float* b1 = (const float*)d_in[2];
    const float* W2 = (const float*)d_in[3];
    const float* b2 = (const float*)d_in[4];
    const float* p  = (const float*)d_in[5];
    const int* src  = (const int*)d_in[6];
    const int* dst  = (const int*)d_in[7];

    const int n_nodes = in_sizes[0] / IN_DIM;   // 100000
    const int n_edges = in_sizes[6];            // 1600000
    float* out = (float*)d_out;

    cudaFuncSetAttribute(k_gemm1, cudaFuncAttributeMaxDynamicSharedMemorySize, G1_SMEM_BYTES);
    cudaFuncSetAttribute(k_gemm2, cudaFuncAttributeMaxDynamicSharedMemorySize, G2_SMEM_BYTES);

    k_zero<<<2048, 256>>>();
    k_degree<<<(n_edges + 255) / 256, 256>>>(src, dst, n_edges);
    k_norm<<<(n_nodes + 255) / 256, 256>>>(n_nodes);
    k_prep<<<2048, 256>>>(h, W1, W2);

    // SpMM1: fp16x2 REDs
    {
        int warps = (n_edges + 7) / 8;
        k_spmm1<<<(warps + 7) / 8, 256>>>(src, dst, n_edges);
    }
    // GEMM1 (fp16 A direct, fp16-split W1, 2 MMA terms)
    {
        dim3 grid(NN_PAD / BM, HID_DIM / BN);   // 782 x 4
        k_gemm1<<<grid, 256, G1_SMEM_BYTES>>>(b1, p, n_nodes);
    }
    // GEMM2 (bf16-split, unchanged)
    {
        dim3 grid(NN_PAD / BM, 1);              // 782
        k_gemm2<<<grid, 256, G2_SMEM_BYTES>>>(n_nodes);
    }
    // SpMM2: fp16x2 REDs, fused norm_dst
    {
        int warps = (n_edges + 7) / 8;
        k_spmm2<<<(warps + 7) / 8, 256>>>(src, dst, n_edges);
    }
    k_final<<<(n_nodes * (OUT_DIM / 4) + 255) / 256, 256>>>(out, b2, n_nodes);
}

// round 16
// speedup vs baseline: 1.6726x; 1.1104x over previous
#include <cuda_runtime.h>
#include <cuda_bf16.h>
#include <cuda_fp16.h>
#include <stdint.h>

#define NN 100000
#define NN_PAD 100096
#define NE 1600000
#define IN_DIM 128
#define HID_DIM 256
#define OUT_DIM 64

// ---------------- device scratch ----------------
__device__ __align__(16) float g_norm_src[NN_PAD];
__device__ __align__(16) float g_norm_dst[NN_PAD];
__device__ __align__(16) __half g_h16[(size_t)NN * IN_DIM];            // fp16(h * norm_src[row])
__device__ __align__(16) __half g_xagg16[(size_t)NN_PAD * IN_DIM];     // fp16 accumulator (RED target)
__device__ __align__(16) __half g_out16[(size_t)NN * OUT_DIM];         // fp16 output accumulator
__device__ __align__(16) __half g_w1t_hi[HID_DIM * IN_DIM];            // fp16 split, [n][k]
__device__ __align__(16) __half g_w1t_lo[HID_DIM * IN_DIM];
__device__ __align__(16) __half g_w2t_hi[OUT_DIM * HID_DIM];           // fp16 split, [n][k]
__device__ __align__(16) __half g_w2t_lo[OUT_DIM * HID_DIM];
__device__ __align__(16) __half g_hid16[(size_t)NN_PAD * HID_DIM];     // fp16 hidden
__device__ __align__(16) __half g_ypre16[(size_t)NN * OUT_DIM];

__device__ __forceinline__ void split_fp16(float v, __half& hi, __half& lo) {
    hi = __float2half_rn(v);
    lo = __float2half_rn(v - __half2float(hi));
}

#define MMA_F16(d, a, b0, b1)                                                   \
    asm volatile("mma.sync.aligned.m16n8k16.row.col.f32.f16.f16.f32 "           \
                 "{%0,%1,%2,%3}, {%4,%5,%6,%7}, {%8,%9}, {%0,%1,%2,%3};"        \
                 : "+f"(d[0]), "+f"(d[1]), "+f"(d[2]), "+f"(d[3])               \
                 : "r"(a[0]), "r"(a[1]), "r"(a[2]), "r"(a[3]), "r"(b0), "r"(b1))

__device__ __forceinline__ void cp16(void* smem_dst, const void* gmem_src) {
    uint32_t s = (uint32_t)__cvta_generic_to_shared(smem_dst);
    asm volatile("cp.async.cg.shared.global [%0], [%1], 16;" :: "r"(s), "l"(gmem_src) : "memory");
}
#define CP_COMMIT() asm volatile("cp.async.commit_group;" ::: "memory")
#define CP_WAIT(n)  asm volatile("cp.async.wait_group %0;" :: "n"(n) : "memory")

// ---------------- zero init ----------------
__global__ void k_zero() {
    int i = blockIdx.x * blockDim.x + threadIdx.x;
    int stride = gridDim.x * blockDim.x;
    const uint4 z4 = make_uint4(0u, 0u, 0u, 0u);
    const int nxa = NN_PAD * (IN_DIM / 8);
    uint4* xa = reinterpret_cast<uint4*>(g_xagg16);
    for (int j = i; j < nxa; j += stride) xa[j] = z4;
    const int nout = NN * (OUT_DIM / 8);
    uint4* o16 = reinterpret_cast<uint4*>(g_out16);
    for (int j = i; j < nout; j += stride) o16[j] = z4;
    for (int j = i; j < NN_PAD; j += stride) { g_norm_src[j] = 0.f; g_norm_dst[j] = 0.f; }
    // hid pad rows (read by gemm2 A tiles) must be zero
    const int hid_pad = (NN_PAD - NN) * (HID_DIM / 8);
    uint4* hh = reinterpret_cast<uint4*>(g_hid16 + (size_t)NN * HID_DIM);
    for (int j = i; j < hid_pad; j += stride) hh[j] = z4;
}

// ---------------- degrees ----------------
__global__ void k_degree(const int* __restrict__ src, const int* __restrict__ dst, int n_edges) {
    int i = blockIdx.x * blockDim.x + threadIdx.x;
    int stride = gridDim.x * blockDim.x;
    for (int e = i; e < n_edges; e += stride) {
        atomicAdd(&g_norm_src[src[e]], 1.0f);
        atomicAdd(&g_norm_dst[dst[e]], 1.0f);
    }
}

__global__ void k_norm(int n_nodes) {
    int i = blockIdx.x * blockDim.x + threadIdx.x;
    if (i < n_nodes) {
        g_norm_src[i] = rsqrtf(fmaxf(g_norm_src[i], 1.0f));
        g_norm_dst[i] = rsqrtf(fmaxf(g_norm_dst[i], 1.0f));
    }
}

// ---------------- prep: h16 = fp16(h * norm_src[row]); W1/W2 fp16-split ----------------
__global__ void k_prep(const float* __restrict__ h,
                       const float* __restrict__ W1, const float* __restrict__ W2) {
    int i = blockIdx.x * blockDim.x + threadIdx.x;
    int stride = gridDim.x * blockDim.x;
    const int n1 = HID_DIM * IN_DIM;
    const int n2 = OUT_DIM * HID_DIM;
    for (int j = i; j < n1 + n2; j += stride) {
        if (j < n1) {
            int n = j / IN_DIM, k = j % IN_DIM;
            float v = W1[(size_t)k * HID_DIM + n];
            __half hi, lo;
            split_fp16(v, hi, lo);
            g_w1t_hi[j] = hi; g_w1t_lo[j] = lo;
        } else {
            int jj = j - n1;
            int n = jj / HID_DIM, k = jj % HID_DIM;
            float v = W2[(size_t)k * OUT_DIM + n];
            __half hi, lo;
            split_fp16(v, hi, lo);
            g_w2t_hi[jj] = hi; g_w2t_lo[jj] = lo;
        }
    }
    const int nh4 = NN * (IN_DIM / 4);
    for (int j = i; j < nh4; j += stride) {
        int row = j >> 5;
        float ns = g_norm_src[row];
        float4 v = reinterpret_cast<const float4*>(h)[j];
        __half2 a = __floats2half2_rn(v.x * ns, v.y * ns);
        __half2 b = __floats2half2_rn(v.z * ns, v.w * ns);
        uint2 pk;
        pk.x = *reinterpret_cast<uint32_t*>(&a);
        pk.y = *reinterpret_cast<uint32_t*>(&b);
        reinterpret_cast<uint2*>(g_h16)[j] = pk;
    }
}

// ---------------- SpMM1: xagg16[dst] += h16[src]  (fp16x2 REDs) ----------------
__global__ void k_spmm1(const int* __restrict__ src, const int* __restrict__ dst,
                        int n_edges) {
    int w = (blockIdx.x * blockDim.x + threadIdx.x) >> 5;
    int lane = threadIdx.x & 31;
    int half_id = lane >> 4;
    int l = lane & 15;
    int e0 = w * 8;
    if (e0 >= n_edges) return;
    int s[4], d[4];
    #pragma unroll
    for (int i = 0; i < 4; i++) {
        int e = min(e0 + 2 * i + half_id, n_edges - 1);
        s[i] = __ldg(&src[e]);
        d[i] = __ldg(&dst[e]);
    }
    uint4 v[4];
    #pragma unroll
    for (int i = 0; i < 4; i++)
        v[i] = reinterpret_cast<const uint4*>(g_h16 + (size_t)s[i] * IN_DIM)[l];
    #pragma unroll
    for (int i = 0; i < 4; i++) {
        if (e0 + 2 * i + half_id >= n_edges) break;
        uint4* orow = reinterpret_cast<uint4*>(g_xagg16 + (size_t)d[i] * IN_DIM);
        asm volatile("red.global.add.noftz.v4.f16x2 [%0], {%1,%2,%3,%4};"
                     :: "l"(orow + l), "r"(v[i].x), "r"(v[i].y), "r"(v[i].z), "r"(v[i].w)
                     : "memory");
    }
}

// ---------------- GEMM tiles ----------------
#define BM 128
#define BN 64
#define BK 32
#define KPAD 40
// stage (halves): As[BM*KPAD]=5120 @0, Bs_hi[BN*KPAD]=2560 @5120, Bs_lo @7680
#define STAGE 10240
#define SMEM_BYTES (2 * STAGE * 2)

// GEMM1: hidden16 = fp16(relu(norm_dst*(xagg16 @ W1) + b1) * clip(p,0,1))
__global__ __launch_bounds__(256) void k_gemm1(const float* __restrict__ b1,
                                               const float* __restrict__ p,
                                               int n_nodes) {
    extern __shared__ __half smem_h[];
    const int m0 = blockIdx.x * BM;
    const int n0 = blockIdx.y * BN;
    const int tid = threadIdx.x;
    const int lane = tid & 31;
    const int wid = tid >> 5;
    const int warp_m = wid >> 2;
    const int warp_n = wid & 3;
    const int bn = tid >> 2;
    const int bq = tid & 3;

    auto load_stage = [&](int s, int k0) {
        __half* As = smem_h + s * STAGE;
        __half* Bs_hi = As + 5120;
        __half* Bs_lo = As + 7680;
        #pragma unroll
        for (int i = 0; i < 2; i++) {
            int idx = tid + 256 * i;
            int row = idx >> 2;
            int q = idx & 3;
            cp16(&As[row * KPAD + 8 * q], &g_xagg16[(size_t)(m0 + row) * IN_DIM + k0 + 8 * q]);
        }
        cp16(&Bs_hi[bn * KPAD + 8 * bq], &g_w1t_hi[(size_t)(n0 + bn) * IN_DIM + k0 + 8 * bq]);
        cp16(&Bs_lo[bn * KPAD + 8 * bq], &g_w1t_lo[(size_t)(n0 + bn) * IN_DIM + k0 + 8 * bq]);
        CP_COMMIT();
    };

    float acc[4][2][4];
    #pragma unroll
    for (int i = 0; i < 4; i++)
        #pragma unroll
        for (int j = 0; j < 2; j++)
            #pragma unroll
            for (int q = 0; q < 4; q++) acc[i][j][q] = 0.f;

    const int K_ITERS = IN_DIM / BK;
    load_stage(0, 0);
    for (int it = 0; it < K_ITERS; it++) {
        if (it + 1 < K_ITERS) {
            load_stage((it + 1) & 1, (it + 1) * BK);
            CP_WAIT(1);
        } else {
            CP_WAIT(0);
        }
        __syncthreads();

        __half* As = smem_h + (it & 1) * STAGE;
        __half* Bs_hi = As + 5120;
        __half* Bs_lo = As + 7680;

        #pragma unroll
        for (int ks = 0; ks < 2; ks++) {
            const int kc = ks * 16 + 2 * (lane & 3);
            uint32_t a[4][4];
            #pragma unroll
            for (int i = 0; i < 4; i++) {
                int r = warp_m * 64 + i * 16 + (lane >> 2);
                a[i][0] = *reinterpret_cast<uint32_t*>(&As[r * KPAD + kc]);
                a[i][1] = *reinterpret_cast<uint32_t*>(&As[(r + 8) * KPAD + kc]);
                a[i][2] = *reinterpret_cast<uint32_t*>(&As[r * KPAD + kc + 8]);
                a[i][3] = *reinterpret_cast<uint32_t*>(&As[(r + 8) * KPAD + kc + 8]);
            }
            #pragma unroll
            for (int j = 0; j < 2; j++) {
                int c = warp_n * 16 + j * 8 + (lane >> 2);
                uint32_t bh0 = *reinterpret_cast<uint32_t*>(&Bs_hi[c * KPAD + kc]);
                uint32_t bh1 = *reinterpret_cast<uint32_t*>(&Bs_hi[c * KPAD + kc + 8]);
                uint32_t bl0 = *reinterpret_cast<uint32_t*>(&Bs_lo[c * KPAD + kc]);
                uint32_t bl1 = *reinterpret_cast<uint32_t*>(&Bs_lo[c * KPAD + kc + 8]);
                #pragma unroll
                for (int i = 0; i < 4; i++) {
                    MMA_F16(acc[i][j], a[i], bh0, bh1);
                    MMA_F16(acc[i][j], a[i], bl0, bl1);
                }
            }
        }
        __syncthreads();
    }

    // epilogue: * norm_dst, + bias, relu, * p, fp16 store
    #pragma unroll
    for (int i = 0; i < 4; i++) {
        int r = warp_m * 64 + i * 16 + (lane >> 2);
        #pragma unroll
        for (int j = 0; j < 2; j++) {
            int c0 = n0 + warp_n * 16 + j * 8 + 2 * (lane & 3);
            float bb0 = b1[c0], bb1 = b1[c0 + 1];
            float p0 = fminf(fmaxf(p[c0], 0.f), 1.f);
            float p1 = fminf(fmaxf(p[c0 + 1], 0.f), 1.f);
            #pragma unroll
            for (int hrow = 0; hrow < 2; hrow++) {
                int grow = m0 + r + 8 * hrow;
                if (grow >= n_nodes) continue;
                float nd = g_norm_dst[grow];
                float v0 = fmaxf(acc[i][j][2 * hrow + 0] * nd + bb0, 0.f) * p0;
                float v1 = fmaxf(acc[i][j][2 * hrow + 1] * nd + bb1, 0.f) * p1;
                __half2 hv = __floats2half2_rn(v0, v1);
                *reinterpret_cast<__half2*>(&g_hid16[(size_t)grow * HID_DIM + c0]) = hv;
            }
        }
    }
}

// GEMM2: ypre16 = fp16((hid16 @ W2) * norm_src[row]); fp16 A direct, fp16-split W2
__global__ __launch_bounds__(256) void k_gemm2(int n_nodes) {
    extern __shared__ __half smem_h[];
    const int m0 = blockIdx.x * BM;
    const int tid = threadIdx.x;
    const int lane = tid & 31;
    const int wid = tid >> 5;
    const int warp_m = wid >> 2;
    const int warp_n = wid & 3;
    const int bn = tid >> 2;
    const int bq = tid & 3;

    auto load_stage = [&](int s, int k0) {
        __half* As = smem_h + s * STAGE;
        __half* Bs_hi = As + 5120;
        __half* Bs_lo = As + 7680;
        #pragma unroll
        for (int i = 0; i < 2; i++) {
            int idx = tid + 256 * i;
            int row = idx >> 2;
            int q = idx & 3;
            cp16(&As[row * KPAD + 8 * q], &g_hid16[(size_t)(m0 + row) * HID_DIM + k0 + 8 * q]);
        }
        cp16(&Bs_hi[bn * KPAD + 8 * bq], &g_w2t_hi[(size_t)bn * HID_DIM + k0 + 8 * bq]);
        cp16(&Bs_lo[bn * KPAD + 8 * bq], &g_w2t_lo[(size_t)bn * HID_DIM + k0 + 8 * bq]);
        CP_COMMIT();
    };

    float acc[4][2][4];
    #pragma unroll
    for (int i = 0; i < 4; i++)
        #pragma unroll
        for (int j = 0; j < 2; j++)
            #pragma unroll
            for (int q = 0; q < 4; q++) acc[i][j][q] = 0.f;

    const int K_ITERS = HID_DIM / BK;
    load_stage(0, 0);
    for (int it = 0; it < K_ITERS; it++) {
        if (it + 1 < K_ITERS) {
            load_stage((it + 1) & 1, (it + 1) * BK);
            CP_WAIT(1);
        } else {
            CP_WAIT(0);
        }
        __syncthreads();

        __half* As = smem_h + (it & 1) * STAGE;
        __half* Bs_hi = As + 5120;
        __half* Bs_lo = As + 7680;

        #pragma unroll
        for (int ks = 0; ks < 2; ks++) {
            const int kc = ks * 16 + 2 * (lane & 3);
            uint32_t a[4][4];
            #pragma unroll
            for (int i = 0; i < 4; i++) {
                int r = warp_m * 64 + i * 16 + (lane >> 2);
                a[i][0] = *reinterpret_cast<uint32_t*>(&As[r * KPAD + kc]);
                a[i][1] = *reinterpret_cast<uint32_t*>(&As[(r + 8) * KPAD + kc]);
                a[i][2] = *reinterpret_cast<uint32_t*>(&As[r * KPAD + kc + 8]);
                a[i][3] = *reinterpret_cast<uint32_t*>(&As[(r + 8) * KPAD + kc + 8]);
            }
            #pragma unroll
            for (int j = 0; j < 2; j++) {
                int c = warp_n * 16 + j * 8 + (lane >> 2);
                uint32_t bh0 = *reinterpret_cast<uint32_t*>(&Bs_hi[c * KPAD + kc]);
                uint32_t bh1 = *reinterpret_cast<uint32_t*>(&Bs_hi[c * KPAD + kc + 8]);
                uint32_t bl0 = *reinterpret_cast<uint32_t*>(&Bs_lo[c * KPAD + kc]);
                uint32_t bl1 = *reinterpret_cast<uint32_t*>(&Bs_lo[c * KPAD + kc + 8]);
                #pragma unroll
                for (int i = 0; i < 4; i++) {
                    MMA_F16(acc[i][j], a[i], bh0, bh1);
                    MMA_F16(acc[i][j], a[i], bl0, bl1);
                }
            }
        }
        __syncthreads();
    }

    #pragma unroll
    for (int i = 0; i < 4; i++) {
        int r = warp_m * 64 + i * 16 + (lane >> 2);
        #pragma unroll
        for (int j = 0; j < 2; j++) {
            int c0 = warp_n * 16 + j * 8 + 2 * (lane & 3);
            #pragma unroll
            for (int hrow = 0; hrow < 2; hrow++) {
                int grow = m0 + r + 8 * hrow;
                if (grow >= n_nodes) continue;
                float ns = g_norm_src[grow];
                __half2 v = __floats2half2_rn(acc[i][j][2 * hrow + 0] * ns,
                                              acc[i][j][2 * hrow + 1] * ns);
                *reinterpret_cast<__half2*>(&g_ypre16[(size_t)grow * OUT_DIM + c0]) = v;
            }
        }
    }
}

// ---------------- SpMM2: out16[dst] += fp16(ypre16[src]*norm_dst[dst]) (fp16x2 REDs) ----------------
__global__ void k_spmm2(const int* __restrict__ src, const int* __restrict__ dst,
                        int n_edges) {
    int w = (blockIdx.x * blockDim.x + threadIdx.x) >> 5;
    int lane = threadIdx.x & 31;
    int half_id = lane >> 4;
    int l = lane & 15;
    int e0 = w * 8;
    if (e0 >= n_edges) return;
    int s[4], d[4];
    #pragma unroll
    for (int i = 0; i < 4; i++) {
        int e = min(e0 + 2 * i + half_id, n_edges - 1);
        s[i] = __ldg(&src[e]);
        d[i] = __ldg(&dst[e]);
    }
    float nd[4];
    #pragma unroll
    for (int i = 0; i < 4; i++) nd[i] = g_norm_dst[d[i]];
    uint2 v[4];
    #pragma unroll
    for (int i = 0; i < 4; i++)
        v[i] = reinterpret_cast<const uint2*>(g_ypre16 + (size_t)s[i] * OUT_DIM)[l];
    #pragma unroll
    for (int i = 0; i < 4; i++) {
        if (e0 + 2 * i + half_id >= n_edges) break;
        __half2 a = *reinterpret_cast<__half2*>(&v[i].x);
        __half2 b = *reinterpret_cast<__half2*>(&v[i].y);
        float2 fa = __half22float2(a);
        float2 fb = __half22float2(b);
        __half2 ta = __floats2half2_rn(fa.x * nd[i], fa.y * nd[i]);
        __half2 tb = __floats2half2_rn(fb.x * nd[i], fb.y * nd[i]);
        uint32_t pa = *reinterpret_cast<uint32_t*>(&ta);
        uint32_t pb = *reinterpret_cast<uint32_t*>(&tb);
        uint2* orow = reinterpret_cast<uint2*>(g_out16 + (size_t)d[i] * OUT_DIM);
        asm volatile("red.global.add.noftz.v2.f16x2 [%0], {%1,%2};"
                     :: "l"(orow + l), "r"(pa), "r"(pb)
                     : "memory");
    }
}

// ---------------- final: out = fp32(out16) + b2[col] ----------------
__global__ void k_final(float* __restrict__ out, const float* __restrict__ b2, int n_nodes) {
    int i = blockIdx.x * blockDim.x + threadIdx.x;
    const int total = n_nodes * (OUT_DIM / 4);
    if (i >= total) return;
    int c4 = i & 15;
    uint2 v = reinterpret_cast<const uint2*>(g_out16)[i];
    float2 f0 = __half22float2(*reinterpret_cast<__half2*>(&v.x));
    float2 f1 = __half22float2(*reinterpret_cast<__half2*>(&v.y));
    const float4 bb = __ldg(&reinterpret_cast<const float4*>(b2)[c4]);
    float4 o;
    o.x = f0.x + bb.x;
    o.y = f0.y + bb.y;
    o.z = f1.x + bb.z;
    o.w = f1.y + bb.w;
    reinterpret_cast<float4*>(out)[i] = o;
}

// ---------------- launch ----------------
extern "C" void kernel_launch(void* const* d_in, const int* in_sizes, int n_in,
                              void* d_out, int out_size) {
    const float* h  = (const float*)d_in[0];
    const float* W1 = (const float*)d_in[1];
    const float* b1 = (const float*)d_in[2];
    const float* W2 = (const float*)d_in[3];
    const float* b2 = (const float*)d_in[4];
    const float* p  = (const float*)d_in[5];
    const int* src  = (const int*)d_in[6];
    const int* dst  = (const int*)d_in[7];

    const int n_nodes = in_sizes[0] / IN_DIM;   // 100000
    const int n_edges = in_sizes[6];            // 1600000
    float* out = (float*)d_out;

    cudaFuncSetAttribute(k_gemm1, cudaFuncAttributeMaxDynamicSharedMemorySize, SMEM_BYTES);
    cudaFuncSetAttribute(k_gemm2, cudaFuncAttributeMaxDynamicSharedMemorySize, SMEM_BYTES);

    k_zero<<<2048, 256>>>();
    k_degree<<<(n_edges + 255) / 256, 256>>>(src, dst, n_edges);
    k_norm<<<(n_nodes + 255) / 256, 256>>>(n_nodes);
    k_prep<<<2048, 256>>>(h, W1, W2);

    // SpMM1: fp16x2 REDs
    {
        int warps = (n_edges + 7) / 8;
        k_spmm1<<<(warps + 7) / 8, 256>>>(src, dst, n_edges);
    }
    // GEMM1 (fp16 A direct, fp16-split W1, 2 MMA terms)
    {
        dim3 grid(NN_PAD / BM, HID_DIM / BN);   // 782 x 4
        k_gemm1<<<grid, 256, SMEM_BYTES>>>(b1, p, n_nodes);
    }
    // GEMM2 (fp16 A direct, fp16-split W2, 2 MMA terms)
    {
        dim3 grid(NN_PAD / BM, 1);              // 782
        k_gemm2<<<grid, 256, SMEM_BYTES>>>(n_nodes);
    }
    // SpMM2: fp16x2 REDs, fused norm_dst
    {
        int warps = (n_edges + 7) / 8;
        k_spmm2<<<(warps + 7) / 8, 256>>>(src, dst, n_edges);
    }
    k_final<<<(n_nodes * (OUT_DIM / 4) + 255) / 256, 256>>>(out, b2, n_nodes);
}

// round 17
// speedup vs baseline: 1.6976x; 1.0149x over previous
#include <cuda_runtime.h>
#include <cuda_bf16.h>
#include <cuda_fp16.h>
#include <stdint.h>

#define NN 100000
#define NN_PAD 100096
#define NE 1600000
#define IN_DIM 128
#define HID_DIM 256
#define OUT_DIM 64

// ---------------- device scratch ----------------
__device__ __align__(16) float g_deg_src[NN];
__device__ __align__(16) float g_deg_dst[NN];
__device__ __align__(16) float g_norm_src[NN_PAD];
__device__ __align__(16) float g_norm_dst[NN_PAD];
__device__ __align__(16) __half g_h16[(size_t)NN * IN_DIM];            // fp16(h * norm_src[row])
__device__ __align__(16) __half g_xagg16[(size_t)NN_PAD * IN_DIM];     // fp16 accumulator (RED target)
__device__ __align__(16) __half g_out16[(size_t)NN * OUT_DIM];         // fp16 output accumulator
__device__ __align__(16) __half g_w1t_hi[HID_DIM * IN_DIM];            // fp16 split, [n][k]
__device__ __align__(16) __half g_w1t_lo[HID_DIM * IN_DIM];
__device__ __align__(16) __half g_w2t_hi[OUT_DIM * HID_DIM];           // fp16 split, [n][k]
__device__ __align__(16) __half g_w2t_lo[OUT_DIM * HID_DIM];
__device__ __align__(16) __half g_hid16[(size_t)NN_PAD * HID_DIM];     // fp16 hidden
__device__ __align__(16) __half g_ypre16[(size_t)NN * OUT_DIM];

__device__ __forceinline__ void split_fp16(float v, __half& hi, __half& lo) {
    hi = __float2half_rn(v);
    lo = __float2half_rn(v - __half2float(hi));
}

#define MMA_F16(d, a, b0, b1)                                                   \
    asm volatile("mma.sync.aligned.m16n8k16.row.col.f32.f16.f16.f32 "           \
                 "{%0,%1,%2,%3}, {%4,%5,%6,%7}, {%8,%9}, {%0,%1,%2,%3};"        \
                 : "+f"(d[0]), "+f"(d[1]), "+f"(d[2]), "+f"(d[3])               \
                 : "r"(a[0]), "r"(a[1]), "r"(a[2]), "r"(a[3]), "r"(b0), "r"(b1))

__device__ __forceinline__ void cp16(void* smem_dst, const void* gmem_src) {
    uint32_t s = (uint32_t)__cvta_generic_to_shared(smem_dst);
    asm volatile("cp.async.cg.shared.global [%0], [%1], 16;" :: "r"(s), "l"(gmem_src) : "memory");
}
#define CP_COMMIT() asm volatile("cp.async.commit_group;" ::: "memory")
#define CP_WAIT(n)  asm volatile("cp.async.wait_group %0;" :: "n"(n) : "memory")

// ---------------- zero init ----------------
__global__ void k_zero() {
    int i = blockIdx.x * blockDim.x + threadIdx.x;
    int stride = gridDim.x * blockDim.x;
    const uint4 z4 = make_uint4(0u, 0u, 0u, 0u);
    const int nxa = NN_PAD * (IN_DIM / 8);
    uint4* xa = reinterpret_cast<uint4*>(g_xagg16);
    for (int j = i; j < nxa; j += stride) xa[j] = z4;
    const int nout = NN * (OUT_DIM / 8);
    uint4* o16 = reinterpret_cast<uint4*>(g_out16);
    for (int j = i; j < nout; j += stride) o16[j] = z4;
    for (int j = i; j < NN; j += stride) { g_deg_src[j] = 0.f; g_deg_dst[j] = 0.f; }
    for (int j = i; j < NN_PAD; j += stride) { g_norm_src[j] = 0.f; g_norm_dst[j] = 0.f; }
    // hid pad rows (read by gemm2 A tiles) must be zero
    const int hid_pad = (NN_PAD - NN) * (HID_DIM / 8);
    uint4* hh = reinterpret_cast<uint4*>(g_hid16 + (size_t)NN * HID_DIM);
    for (int j = i; j < hid_pad; j += stride) hh[j] = z4;
}

// ---------------- degrees ----------------
__global__ void k_degree(const int* __restrict__ src, const int* __restrict__ dst, int n_edges) {
    int i = blockIdx.x * blockDim.x + threadIdx.x;
    int stride = gridDim.x * blockDim.x;
    for (int e = i; e < n_edges; e += stride) {
        atomicAdd(&g_deg_src[src[e]], 1.0f);
        atomicAdd(&g_deg_dst[dst[e]], 1.0f);
    }
}

// ---------------- prep: norms; h16 = fp16(h * norm_src[row]); W1/W2 fp16-split ----------------
__global__ void k_prep(const float* __restrict__ h,
                       const float* __restrict__ W1, const float* __restrict__ W2) {
    int i = blockIdx.x * blockDim.x + threadIdx.x;
    int stride = gridDim.x * blockDim.x;
    // norms (for later kernels)
    for (int j = i; j < NN; j += stride) {
        g_norm_src[j] = rsqrtf(fmaxf(g_deg_src[j], 1.0f));
        g_norm_dst[j] = rsqrtf(fmaxf(g_deg_dst[j], 1.0f));
    }
    // weights
    const int n1 = HID_DIM * IN_DIM;
    const int n2 = OUT_DIM * HID_DIM;
    for (int j = i; j < n1 + n2; j += stride) {
        if (j < n1) {
            int n = j / IN_DIM, k = j % IN_DIM;
            float v = W1[(size_t)k * HID_DIM + n];
            __half hi, lo;
            split_fp16(v, hi, lo);
            g_w1t_hi[j] = hi; g_w1t_lo[j] = lo;
        } else {
            int jj = j - n1;
            int n = jj / HID_DIM, k = jj % HID_DIM;
            float v = W2[(size_t)k * OUT_DIM + n];
            __half hi, lo;
            split_fp16(v, hi, lo);
            g_w2t_hi[jj] = hi; g_w2t_lo[jj] = lo;
        }
    }
    // h16 with norm_src folded in (compute rsqrt from raw degree; no race on norm arrays)
    const int nh4 = NN * (IN_DIM / 4);
    for (int j = i; j < nh4; j += stride) {
        int row = j >> 5;
        float ns = rsqrtf(fmaxf(__ldg(&g_deg_src[row]), 1.0f));
        float4 v = reinterpret_cast<const float4*>(h)[j];
        __half2 a = __floats2half2_rn(v.x * ns, v.y * ns);
        __half2 b = __floats2half2_rn(v.z * ns, v.w * ns);
        uint2 pk;
        pk.x = *reinterpret_cast<uint32_t*>(&a);
        pk.y = *reinterpret_cast<uint32_t*>(&b);
        reinterpret_cast<uint2*>(g_h16)[j] = pk;
    }
}

// ---------------- SpMM1: xagg16[dst] += h16[src]  (fp16x2 REDs) ----------------
__global__ void k_spmm1(const int* __restrict__ src, const int* __restrict__ dst,
                        int n_edges) {
    int w = (blockIdx.x * blockDim.x + threadIdx.x) >> 5;
    int lane = threadIdx.x & 31;
    int half_id = lane >> 4;
    int l = lane & 15;
    int e0 = w * 8;
    if (e0 >= n_edges) return;
    int s[4], d[4];
    #pragma unroll
    for (int i = 0; i < 4; i++) {
        int e = min(e0 + 2 * i + half_id, n_edges - 1);
        s[i] = __ldg(&src[e]);
        d[i] = __ldg(&dst[e]);
    }
    uint4 v[4];
    #pragma unroll
    for (int i = 0; i < 4; i++)
        v[i] = reinterpret_cast<const uint4*>(g_h16 + (size_t)s[i] * IN_DIM)[l];
    #pragma unroll
    for (int i = 0; i < 4; i++) {
        if (e0 + 2 * i + half_id >= n_edges) break;
        uint4* orow = reinterpret_cast<uint4*>(g_xagg16 + (size_t)d[i] * IN_DIM);
        asm volatile("red.global.add.noftz.v4.f16x2 [%0], {%1,%2,%3,%4};"
                     :: "l"(orow + l), "r"(v[i].x), "r"(v[i].y), "r"(v[i].z), "r"(v[i].w)
                     : "memory");
    }
}

// ---------------- GEMM tiles ----------------
#define BM 128
#define BN 64
#define BK 32
#define KPAD 40
// gemm1: A fully resident (128 x 136 halves), B double-buffered (2 x 5120 halves)
#define KPA 136
#define G1_AFULL (128 * KPA)          // 17408
#define G1_BSTAGE 5120                // Bs_hi 2560 + Bs_lo 2560
#define G1_SMEM_BYTES ((G1_AFULL + 2 * G1_BSTAGE) * 2)   // 55296
// gemm2: double-buffered stage (halves): As 5120 @0, Bs_hi @5120, Bs_lo @7680
#define STAGE 10240
#define G2_SMEM_BYTES (2 * STAGE * 2)

// GEMM1: hidden16 = fp16(relu(norm_dst*(xagg16 @ W1) + b1) * clip(p,0,1))
// A resident in smem (read once from gmem); 16 macro-steps (4 n-chunks x 4 k-chunks)
__global__ __launch_bounds__(256) void k_gemm1(const float* __restrict__ b1,
                                               const float* __restrict__ p,
                                               int n_nodes) {
    extern __shared__ __half smem_h[];
    __half* Af = smem_h;
    const int m0 = blockIdx.x * BM;
    const int tid = threadIdx.x;
    const int lane = tid & 31;
    const int wid = tid >> 5;
    const int warp_m = wid >> 2;
    const int warp_n = wid & 3;
    const int bn = tid >> 2;
    const int bq = tid & 3;

    // load all of A: 2048 16B chunks, 8/thread (group 0)
    #pragma unroll
    for (int i = 0; i < 8; i++) {
        int idx = tid + 256 * i;
        int row = idx >> 4;          // 16 chunks per row
        int q = idx & 15;
        cp16(&Af[row * KPA + 8 * q], &g_xagg16[(size_t)(m0 + row) * IN_DIM + 8 * q]);
    }
    CP_COMMIT();

    auto load_B = [&](int m) {
        int s = m & 1, nc = m >> 2, it = m & 3;
        int k0 = it * BK, n0 = nc * 64;
        __half* Bs_hi = smem_h + G1_AFULL + s * G1_BSTAGE;
        __half* Bs_lo = Bs_hi + 2560;
        cp16(&Bs_hi[bn * KPAD + 8 * bq], &g_w1t_hi[(size_t)(n0 + bn) * IN_DIM + k0 + 8 * bq]);
        cp16(&Bs_lo[bn * KPAD + 8 * bq], &g_w1t_lo[(size_t)(n0 + bn) * IN_DIM + k0 + 8 * bq]);
        CP_COMMIT();
    };

    float acc[4][2][4];
    #pragma unroll
    for (int i = 0; i < 4; i++)
        #pragma unroll
        for (int j = 0; j < 2; j++)
            #pragma unroll
            for (int q = 0; q < 4; q++) acc[i][j][q] = 0.f;

    load_B(0);
    for (int m = 0; m < 16; m++) {
        if (m + 1 < 16) {
            load_B(m + 1);
            CP_WAIT(1);
        } else {
            CP_WAIT(0);
        }
        __syncthreads();

        const int it = m & 3;
        const int k0 = it * BK;
        __half* Bs_hi = smem_h + G1_AFULL + (m & 1) * G1_BSTAGE;
        __half* Bs_lo = Bs_hi + 2560;

        #pragma unroll
        for (int ks = 0; ks < 2; ks++) {
            const int kcB = ks * 16 + 2 * (lane & 3);
            const int kcA = k0 + kcB;
            uint32_t a[4][4];
            #pragma unroll
            for (int i = 0; i < 4; i++) {
                int r = warp_m * 64 + i * 16 + (lane >> 2);
                a[i][0] = *reinterpret_cast<uint32_t*>(&Af[r * KPA + kcA]);
                a[i][1] = *reinterpret_cast<uint32_t*>(&Af[(r + 8) * KPA + kcA]);
                a[i][2] = *reinterpret_cast<uint32_t*>(&Af[r * KPA + kcA + 8]);
                a[i][3] = *reinterpret_cast<uint32_t*>(&Af[(r + 8) * KPA + kcA + 8]);
            }
            #pragma unroll
            for (int j = 0; j < 2; j++) {
                int c = warp_n * 16 + j * 8 + (lane >> 2);
                uint32_t bh0 = *reinterpret_cast<uint32_t*>(&Bs_hi[c * KPAD + kcB]);
                uint32_t bh1 = *reinterpret_cast<uint32_t*>(&Bs_hi[c * KPAD + kcB + 8]);
                uint32_t bl0 = *reinterpret_cast<uint32_t*>(&Bs_lo[c * KPAD + kcB]);
                uint32_t bl1 = *reinterpret_cast<uint32_t*>(&Bs_lo[c * KPAD + kcB + 8]);
                #pragma unroll
                for (int i = 0; i < 4; i++) {
                    MMA_F16(acc[i][j], a[i], bh0, bh1);
                    MMA_F16(acc[i][j], a[i], bl0, bl1);
                }
            }
        }
        __syncthreads();

        if ((m & 3) == 3) {
            // epilogue for n-chunk nc = m>>2
            const int n0 = (m >> 2) * 64;
            #pragma unroll
            for (int i = 0; i < 4; i++) {
                int r = warp_m * 64 + i * 16 + (lane >> 2);
                #pragma unroll
                for (int j = 0; j < 2; j++) {
                    int c0 = n0 + warp_n * 16 + j * 8 + 2 * (lane & 3);
                    float bb0 = b1[c0], bb1 = b1[c0 + 1];
                    float p0 = fminf(fmaxf(p[c0], 0.f), 1.f);
                    float p1 = fminf(fmaxf(p[c0 + 1], 0.f), 1.f);
                    #pragma unroll
                    for (int hrow = 0; hrow < 2; hrow++) {
                        int grow = m0 + r + 8 * hrow;
                        if (grow >= n_nodes) continue;
                        float nd = g_norm_dst[grow];
                        float v0 = fmaxf(acc[i][j][2 * hrow + 0] * nd + bb0, 0.f) * p0;
                        float v1 = fmaxf(acc[i][j][2 * hrow + 1] * nd + bb1, 0.f) * p1;
                        __half2 hv = __floats2half2_rn(v0, v1);
                        *reinterpret_cast<__half2*>(&g_hid16[(size_t)grow * HID_DIM + c0]) = hv;
                    }
                }
            }
            #pragma unroll
            for (int i = 0; i < 4; i++)
                #pragma unroll
                for (int j = 0; j < 2; j++)
                    #pragma unroll
                    for (int q = 0; q < 4; q++) acc[i][j][q] = 0.f;
        }
    }
}

// GEMM2: ypre16 = fp16((hid16 @ W2) * norm_src[row]); fp16 A direct, fp16-split W2
__global__ __launch_bounds__(256) void k_gemm2(int n_nodes) {
    extern __shared__ __half smem_h[];
    const int m0 = blockIdx.x * BM;
    const int tid = threadIdx.x;
    const int lane = tid & 31;
    const int wid = tid >> 5;
    const int warp_m = wid >> 2;
    const int warp_n = wid & 3;
    const int bn = tid >> 2;
    const int bq = tid & 3;

    auto load_stage = [&](int s, int k0) {
        __half* As = smem_h + s * STAGE;
        __half* Bs_hi = As + 5120;
        __half* Bs_lo = As + 7680;
        #pragma unroll
        for (int i = 0; i < 2; i++) {
            int idx = tid + 256 * i;
            int row = idx >> 2;
            int q = idx & 3;
            cp16(&As[row * KPAD + 8 * q], &g_hid16[(size_t)(m0 + row) * HID_DIM + k0 + 8 * q]);
        }
        cp16(&Bs_hi[bn * KPAD + 8 * bq], &g_w2t_hi[(size_t)bn * HID_DIM + k0 + 8 * bq]);
        cp16(&Bs_lo[bn * KPAD + 8 * bq], &g_w2t_lo[(size_t)bn * HID_DIM + k0 + 8 * bq]);
        CP_COMMIT();
    };

    float acc[4][2][4];
    #pragma unroll
    for (int i = 0; i < 4; i++)
        #pragma unroll
        for (int j = 0; j < 2; j++)
            #pragma unroll
            for (int q = 0; q < 4; q++) acc[i][j][q] = 0.f;

    const int K_ITERS = HID_DIM / BK;
    load_stage(0, 0);
    for (int it = 0; it < K_ITERS; it++) {
        if (it + 1 < K_ITERS) {
            load_stage((it + 1) & 1, (it + 1) * BK);
            CP_WAIT(1);
        } else {
            CP_WAIT(0);
        }
        __syncthreads();

        __half* As = smem_h + (it & 1) * STAGE;
        __half* Bs_hi = As + 5120;
        __half* Bs_lo = As + 7680;

        #pragma unroll
        for (int ks = 0; ks < 2; ks++) {
            const int kc = ks * 16 + 2 * (lane & 3);
            uint32_t a[4][4];
            #pragma unroll
            for (int i = 0; i < 4; i++) {
                int r = warp_m * 64 + i * 16 + (lane >> 2);
                a[i][0] = *reinterpret_cast<uint32_t*>(&As[r * KPAD + kc]);
                a[i][1] = *reinterpret_cast<uint32_t*>(&As[(r + 8) * KPAD + kc]);
                a[i][2] = *reinterpret_cast<uint32_t*>(&As[r * KPAD + kc + 8]);
                a[i][3] = *reinterpret_cast<uint32_t*>(&As[(r + 8) * KPAD + kc + 8]);
            }
            #pragma unroll
            for (int j = 0; j < 2; j++) {
                int c = warp_n * 16 + j * 8 + (lane >> 2);
                uint32_t bh0 = *reinterpret_cast<uint32_t*>(&Bs_hi[c * KPAD + kc]);
                uint32_t bh1 = *reinterpret_cast<uint32_t*>(&Bs_hi[c * KPAD + kc + 8]);
                uint32_t bl0 = *reinterpret_cast<uint32_t*>(&Bs_lo[c * KPAD + kc]);
                uint32_t bl1 = *reinterpret_cast<uint32_t*>(&Bs_lo[c * KPAD + kc + 8]);
                #pragma unroll
                for (int i = 0; i < 4; i++) {
                    MMA_F16(acc[i][j], a[i], bh0, bh1);
                    MMA_F16(acc[i][j], a[i], bl0, bl1);
                }
            }
        }
        __syncthreads();
    }

    #pragma unroll
    for (int i = 0; i < 4; i++) {
        int r = warp_m * 64 + i * 16 + (lane >> 2);
        #pragma unroll
        for (int j = 0; j < 2; j++) {
            int c0 = warp_n * 16 + j * 8 + 2 * (lane & 3);
            #pragma unroll
            for (int hrow = 0; hrow < 2; hrow++) {
                int grow = m0 + r + 8 * hrow;
                if (grow >= n_nodes) continue;
                float ns = g_norm_src[grow];
                __half2 v = __floats2half2_rn(acc[i][j][2 * hrow + 0] * ns,
                                              acc[i][j][2 * hrow + 1] * ns);
                *reinterpret_cast<__half2*>(&g_ypre16[(size_t)grow * OUT_DIM + c0]) = v;
            }
        }
    }
}

// ---------------- SpMM2: out16[dst] += fp16(ypre16[src]*norm_dst[dst]) (fp16x2 REDs) ----------------
__global__ void k_spmm2(const int* __restrict__ src, const int* __restrict__ dst,
                        int n_edges) {
    int w = (blockIdx.x * blockDim.x + threadIdx.x) >> 5;
    int lane = threadIdx.x & 31;
    int half_id = lane >> 4;
    int l = lane & 15;
    int e0 = w * 8;
    if (e0 >= n_edges) return;
    int s[4], d[4];
    #pragma unroll
    for (int i = 0; i < 4; i++) {
        int e = min(e0 + 2 * i + half_id, n_edges - 1);
        s[i] = __ldg(&src[e]);
        d[i] = __ldg(&dst[e]);
    }
    float nd[4];
    #pragma unroll
    for (int i = 0; i < 4; i++) nd[i] = g_norm_dst[d[i]];
    uint2 v[4];
    #pragma unroll
    for (int i = 0; i < 4; i++)
        v[i] = reinterpret_cast<const uint2*>(g_ypre16 + (size_t)s[i] * OUT_DIM)[l];
    #pragma unroll
    for (int i = 0; i < 4; i++) {
        if (e0 + 2 * i + half_id >= n_edges) break;
        __half2 a = *reinterpret_cast<__half2*>(&v[i].x);
        __half2 b = *reinterpret_cast<__half2*>(&v[i].y);
        float2 fa = __half22float2(a);
        float2 fb = __half22float2(b);
        __half2 ta = __floats2half2_rn(fa.x * nd[i], fa.y * nd[i]);
        __half2 tb = __floats2half2_rn(fb.x * nd[i], fb.y * nd[i]);
        uint32_t pa = *reinterpret_cast<uint32_t*>(&ta);
        uint32_t pb = *reinterpret_cast<uint32_t*>(&tb);
        uint2* orow = reinterpret_cast<uint2*>(g_out16 + (size_t)d[i] * OUT_DIM);
        asm volatile("red.global.add.noftz.v2.f16x2 [%0], {%1,%2};"
                     :: "l"(orow + l), "r"(pa), "r"(pb)
                     : "memory");
    }
}

// ---------------- final: out = fp32(out16) + b2[col] ----------------
__global__ void k_final(float* __restrict__ out, const float* __restrict__ b2, int n_nodes) {
    int i = blockIdx.x * blockDim.x + threadIdx.x;
    const int total = n_nodes * (OUT_DIM / 4);
    if (i >= total) return;
    int c4 = i & 15;
    uint2 v = reinterpret_cast<const uint2*>(g_out16)[i];
    float2 f0 = __half22float2(*reinterpret_cast<__half2*>(&v.x));
    float2 f1 = __half22float2(*reinterpret_cast<__half2*>(&v.y));
    const float4 bb = __ldg(&reinterpret_cast<const float4*>(b2)[c4]);
    float4 o;
    o.x = f0.x + bb.x;
    o.y = f0.y + bb.y;
    o.z = f1.x + bb.z;
    o.w = f1.y + bb.w;
    reinterpret_cast<float4*>(out)[i] = o;
}

// ---------------- launch ----------------
extern "C" void kernel_launch(void* const* d_in, const int* in_sizes, int n_in,
                              void* d_out, int out_size) {
    const float* h  = (const float*)d_in[0];
    const float* W1 = (const float*)d_in[1];
    const float* b1 = (const float*)d_in[2];
    const float* W2 = (const float*)d_in[3];
    const float* b2 = (const float*)d_in[4];
    const float* p  = (const float*)d_in[5];
    const int* src  = (const int*)d_in[6];
    const int* dst  = (const int*)d_in[7];

    const int n_nodes = in_sizes[0] / IN_DIM;   // 100000
    const int n_edges = in_sizes[6];            // 1600000
    float* out = (float*)d_out;

    cudaFuncSetAttribute(k_gemm1, cudaFuncAttributeMaxDynamicSharedMemorySize, G1_SMEM_BYTES);
    cudaFuncSetAttribute(k_gemm2, cudaFuncAttributeMaxDynamicSharedMemorySize, G2_SMEM_BYTES);

    k_zero<<<2048, 256>>>();
    k_degree<<<(n_edges + 255) / 256, 256>>>(src, dst, n_edges);
    k_prep<<<2048, 256>>>(h, W1, W2);

    // SpMM1: fp16x2 REDs
    {
        int warps = (n_edges + 7) / 8;
        k_spmm1<<<(warps + 7) / 8, 256>>>(src, dst, n_edges);
    }
    // GEMM1 (A smem-resident, B double-buffered over 16 macro-steps)
    {
        dim3 grid(NN_PAD / BM, 1);              // 782
        k_gemm1<<<grid, 256, G1_SMEM_BYTES>>>(b1, p, n_nodes);
    }
    // GEMM2 (fp16 A direct, fp16-split W2, 2 MMA terms)
    {
        dim3 grid(NN_PAD / BM, 1);              // 782
        k_gemm2<<<grid, 256, G2_SMEM_BYTES>>>(n_nodes);
    }
    // SpMM2: fp16x2 REDs, fused norm_dst
    {
        int warps = (n_edges + 7) / 8;
        k_spmm2<<<(warps + 7) / 8, 256>>>(src, dst, n_edges);
    }
    k_final<<<(n_nodes * (OUT_DIM / 4) + 255) / 256, 256>>>(out, b2, n_nodes);
}